// round 14
// baseline (speedup 1.0000x reference)
#include <cuda_runtime.h>
#include <cuda_bf16.h>
#include <math.h>
#include <stdint.h>

// ---------------- Problem-size constants (fixed by the dataset) -------------
#define NMAX   40000
#define EMAX   640000
#define ETMAX  (EMAX + NMAX)      // edges + self loops
#define CIN    256
#define HDIM   256
#define COUT   512
#define KDIM   256                // every GEMM in this model has K = 256

// ---------------- Static device scratch (no allocation allowed) -------------
__device__ float g_bufA[(size_t)NMAX * HDIM];
__device__ float g_bufB[(size_t)NMAX * HDIM];
__device__ float g_bufH[(size_t)NMAX * HDIM];
__device__ float g_asrc[NMAX];
__device__ float g_adst[NMAX];
__device__ int   g_deg[NMAX];
__device__ int   g_off[NMAX + 1];
__device__ int   g_cursor[NMAX];
__device__ int   g_srcs[ETMAX];
__device__ int   g_is64;          // 1 if edge_index is int64, 0 if int32
__device__ int   g_blksum[64];
__device__ int   g_blkoff[64];

// Buffer-id resolution (device side).
#define BUF_A 0
#define BUF_B 1
#define BUF_H 2
#define BUF_EXT (-1)

__device__ __forceinline__ float* resolve_buf(int id, float* ext)
{
    switch (id) {
        case BUF_A: return g_bufA;
        case BUF_B: return g_bufB;
        case BUF_H: return g_bufH;
        default:    return ext;
    }
}
__device__ __forceinline__ const float* resolve_cbuf(int id, const float* ext)
{
    switch (id) {
        case BUF_A: return g_bufA;
        case BUF_B: return g_bufB;
        case BUF_H: return g_bufH;
        default:    return ext;
    }
}

// ---------------- bf16 helpers ----------------------------------------------
__device__ __forceinline__ void bf16_split(float a, __nv_bfloat16& hi, __nv_bfloat16& lo)
{
    hi = __float2bfloat16_rn(a);
    lo = __float2bfloat16_rn(a - __bfloat162float(hi));
}
__device__ __forceinline__ uint32_t pack_bf16(__nv_bfloat16 a, __nv_bfloat16 b)
{
    return (uint32_t)__bfloat16_as_ushort(a) | ((uint32_t)__bfloat16_as_ushort(b) << 16);
}

__device__ __forceinline__ void mma_bf16(float& c0, float& c1, float& c2, float& c3,
                                         uint32_t a0, uint32_t a1, uint32_t a2, uint32_t a3,
                                         uint32_t b0, uint32_t b1)
{
    asm volatile(
        "mma.sync.aligned.m16n8k16.row.col.f32.bf16.bf16.f32 "
        "{%0,%1,%2,%3}, {%4,%5,%6,%7}, {%8,%9}, {%0,%1,%2,%3};"
        : "+f"(c0), "+f"(c1), "+f"(c2), "+f"(c3)
        : "r"(a0), "r"(a1), "r"(a2), "r"(a3), "r"(b0), "r"(b1));
}

__device__ __forceinline__ float elu_f(float y)
{
    return (y > 0.f) ? y : expm1f(y);
}

// =====================================================================
// 3-pass split-bf16 tensor-core GEMM:  C[m][j] = sum_k A[m][k]*W[j][k]
// Tile BM=128, BN=128, BK=16; 256 threads = 8 warps in 4(M) x 2(N);
// each warp computes 32x64 via 2x8 m16n8k16 fragments.
// Register prefetch + smem ping-pong => one __syncthreads per K-iter.
// Optional fused GroupNorm(8)+ELU epilogue.
// =====================================================================
#define SB32 12    // row stride in u32 (24 bf16 = 48B; (12r+q) mod 32 conflict-free)

template <bool ACC, bool BIAS, bool GNELU>
__global__ void __launch_bounds__(256, 1)
bfgemm_kernel(int A_id, const float* __restrict__ A_ext,
              const float* __restrict__ W,
              const float* __restrict__ bias,
              const float* __restrict__ gn_w,
              const float* __restrict__ gn_b,
              int C_id, float* __restrict__ C_ext,
              int Nrows, int J)
{
    const float* A = resolve_cbuf(A_id, A_ext);
    float* C = resolve_buf(C_id, C_ext);

    __shared__ uint32_t As_hi[2][128 * SB32];
    __shared__ uint32_t As_lo[2][128 * SB32];
    __shared__ uint32_t Bs_hi[2][128 * SB32];
    __shared__ uint32_t Bs_lo[2][128 * SB32];

    int tid  = threadIdx.x;
    int wid  = tid >> 5;
    int lane = tid & 31;
    int grp  = lane >> 2;      // 0..7
    int qid  = lane & 3;       // 0..3

    int m0 = blockIdx.y * 128;
    int j0 = blockIdx.x * 128;

    int wm = (wid >> 1) * 32;  // warp M slab (4 slabs)
    int wn = (wid & 1) * 64;   // warp N slab (2 slabs of 64)

    float acc[2][8][4];
#pragma unroll
    for (int i = 0; i < 2; i++)
#pragma unroll
        for (int j = 0; j < 8; j++)
#pragma unroll
            for (int q = 0; q < 4; q++) acc[i][j][q] = 0.f;

    // loader mapping: each thread loads 8 f32 of A and 8 f32 of B per iter
    int a_row  = tid >> 1;         // 0..127
    int a_half = tid & 1;          // k offset 0 / 8
    int a_grow = m0 + a_row;
    bool a_ok  = (a_grow < Nrows);
    const float* aptr = A + (size_t)a_grow * KDIM + a_half * 8;
    const float* bptr = W + (size_t)(j0 + a_row) * KDIM + a_half * 8;

    uint32_t st_off = a_row * SB32 + a_half * 4;

    // prefetch chunk 0
    float4 av0, av1, bv0, bv1;
    av0 = a_ok ? *(const float4*)(aptr)     : make_float4(0.f, 0.f, 0.f, 0.f);
    av1 = a_ok ? *(const float4*)(aptr + 4) : make_float4(0.f, 0.f, 0.f, 0.f);
    bv0 = *(const float4*)(bptr);
    bv1 = *(const float4*)(bptr + 4);

    for (int it = 0; it < 16; it++) {
        int pp = it & 1;
        // ---- convert + store current chunk into ping-pong slot ----
        {
            float va[8] = {av0.x, av0.y, av0.z, av0.w, av1.x, av1.y, av1.z, av1.w};
            float vb[8] = {bv0.x, bv0.y, bv0.z, bv0.w, bv1.x, bv1.y, bv1.z, bv1.w};
            uint32_t wh[4], wl[4];
#pragma unroll
            for (int i = 0; i < 4; i++) {
                __nv_bfloat16 h0, l0, h1, l1;
                bf16_split(va[2 * i],     h0, l0);
                bf16_split(va[2 * i + 1], h1, l1);
                wh[i] = pack_bf16(h0, h1);
                wl[i] = pack_bf16(l0, l1);
            }
            *(uint4*)(As_hi[pp] + st_off) = make_uint4(wh[0], wh[1], wh[2], wh[3]);
            *(uint4*)(As_lo[pp] + st_off) = make_uint4(wl[0], wl[1], wl[2], wl[3]);
#pragma unroll
            for (int i = 0; i < 4; i++) {
                __nv_bfloat16 h0, l0, h1, l1;
                bf16_split(vb[2 * i],     h0, l0);
                bf16_split(vb[2 * i + 1], h1, l1);
                wh[i] = pack_bf16(h0, h1);
                wl[i] = pack_bf16(l0, l1);
            }
            *(uint4*)(Bs_hi[pp] + st_off) = make_uint4(wh[0], wh[1], wh[2], wh[3]);
            *(uint4*)(Bs_lo[pp] + st_off) = make_uint4(wl[0], wl[1], wl[2], wl[3]);
        }

        // ---- prefetch next chunk ----
        if (it < 15) {
            int k0 = (it + 1) * 16;
            av0 = a_ok ? *(const float4*)(aptr + k0)     : make_float4(0.f, 0.f, 0.f, 0.f);
            av1 = a_ok ? *(const float4*)(aptr + k0 + 4) : make_float4(0.f, 0.f, 0.f, 0.f);
            bv0 = *(const float4*)(bptr + k0);
            bv1 = *(const float4*)(bptr + k0 + 4);
        }

        __syncthreads();   // single barrier per iter (ping-pong protects reuse)

        // ---- A fragment loads (2 m-tiles, hi & lo) ----
        uint32_t ah[2][4], al[2][4];
#pragma unroll
        for (int mt = 0; mt < 2; mt++) {
            int r0 = (wm + mt * 16 + grp) * SB32 + qid;
            int r1 = r0 + 8 * SB32;
            ah[mt][0] = As_hi[pp][r0];     ah[mt][1] = As_hi[pp][r1];
            ah[mt][2] = As_hi[pp][r0 + 4]; ah[mt][3] = As_hi[pp][r1 + 4];
            al[mt][0] = As_lo[pp][r0];     al[mt][1] = As_lo[pp][r1];
            al[mt][2] = As_lo[pp][r0 + 4]; al[mt][3] = As_lo[pp][r1 + 4];
        }
        // ---- per n-tile: load B frag, 3-pass MMA into both m-tiles ----
#pragma unroll
        for (int nt = 0; nt < 8; nt++) {
            int rb = (wn + nt * 8 + grp) * SB32 + qid;
            uint32_t bh0 = Bs_hi[pp][rb], bh1 = Bs_hi[pp][rb + 4];
            uint32_t bl0 = Bs_lo[pp][rb], bl1 = Bs_lo[pp][rb + 4];
#pragma unroll
            for (int mt = 0; mt < 2; mt++) {
                float* c = acc[mt][nt];
                mma_bf16(c[0], c[1], c[2], c[3],
                         ah[mt][0], ah[mt][1], ah[mt][2], ah[mt][3], bh0, bh1);
                mma_bf16(c[0], c[1], c[2], c[3],
                         ah[mt][0], ah[mt][1], ah[mt][2], ah[mt][3], bl0, bl1);
                mma_bf16(c[0], c[1], c[2], c[3],
                         al[mt][0], al[mt][1], al[mt][2], al[mt][3], bh0, bh1);
            }
        }
    }

    // ---- epilogue (optionally fused GroupNorm(8)+ELU) ----
#pragma unroll
    for (int mt = 0; mt < 2; mt++) {
        int row0 = m0 + wm + mt * 16 + grp;
        int row1 = row0 + 8;
#pragma unroll
        for (int nt = 0; nt < 8; nt++) {
            int col = j0 + wn + nt * 8 + qid * 2;
            float b0 = 0.f, b1 = 0.f;
            if (BIAS) { b0 = bias[col]; b1 = bias[col + 1]; }
            float v0 = acc[mt][nt][0] + b0;
            float v1 = acc[mt][nt][1] + b1;
            float v2 = acc[mt][nt][2] + b0;
            float v3 = acc[mt][nt][3] + b1;
            if (GNELU) {
                float s01 = v0 + v1, q01 = v0 * v0 + v1 * v1;
                float s23 = v2 + v3, q23 = v2 * v2 + v3 * v3;
                s01 += __shfl_xor_sync(0xffffffffu, s01, 1);
                q01 += __shfl_xor_sync(0xffffffffu, q01, 1);
                s23 += __shfl_xor_sync(0xffffffffu, s23, 1);
                q23 += __shfl_xor_sync(0xffffffffu, q23, 1);
                s01 += __shfl_xor_sync(0xffffffffu, s01, 2);
                q01 += __shfl_xor_sync(0xffffffffu, q01, 2);
                s23 += __shfl_xor_sync(0xffffffffu, s23, 2);
                q23 += __shfl_xor_sync(0xffffffffu, q23, 2);
                float mu0 = s01 * 0.125f;
                float iv0 = rsqrtf(q01 * 0.125f - mu0 * mu0 + 1e-5f);
                float mu1 = s23 * 0.125f;
                float iv1 = rsqrtf(q23 * 0.125f - mu1 * mu1 + 1e-5f);
                float w0 = gn_w[col], w1 = gn_w[col + 1];
                float gb0 = gn_b[col], gb1 = gn_b[col + 1];
                v0 = elu_f((v0 - mu0) * iv0 * w0 + gb0);
                v1 = elu_f((v1 - mu0) * iv0 * w1 + gb1);
                v2 = elu_f((v2 - mu1) * iv1 * w0 + gb0);
                v3 = elu_f((v3 - mu1) * iv1 * w1 + gb1);
            }
            if (row0 < Nrows) {
                float* p = C + (size_t)row0 * J + col;
                if (ACC) { v0 += p[0]; v1 += p[1]; }
                p[0] = v0; p[1] = v1;
            }
            if (row1 < Nrows) {
                float* p = C + (size_t)row1 * J + col;
                if (ACC) { v2 += p[0]; v3 += p[1]; }
                p[0] = v2; p[1] = v3;
            }
        }
    }
}

// Read edge endpoint idx (0..2E-1 flattened) honoring detected dtype.
__device__ __forceinline__ int edge_at(const void* ei, long long flat)
{
    if (g_is64) return (int)((const long long*)ei)[flat];
    return ((const int*)ei)[flat];
}

__global__ void detect_dtype_kernel(const void* ei, int n)
{
    if (threadIdx.x == 0 && blockIdx.x == 0) {
        const long long* p = (const long long*)ei;
        int ok = 1;
        for (int i = 0; i < 64; i++) {
            long long v = p[i];
            if (v < 0 || v >= n) { ok = 0; break; }
        }
        g_is64 = ok;
    }
}

// =====================================================================
// GroupNorm(groups = C/8) + ELU (standalone; used only for pre_norm).
// =====================================================================
__global__ void gnelu_kernel(int in_id, const float* __restrict__ in_ext,
                             const float* __restrict__ w,
                             const float* __restrict__ b,
                             int out_id, int n)
{
    const float* in = resolve_cbuf(in_id, in_ext);
    float* out = resolve_buf(out_id, nullptr);
    int warp = (blockIdx.x * blockDim.x + threadIdx.x) >> 5;
    int lane = threadIdx.x & 31;
    if (warp >= n) return;
    const float* row = in + (size_t)warp * 256;
    int c0 = lane * 8;
    float4 v0 = *(const float4*)(row + c0);
    float4 v1 = *(const float4*)(row + c0 + 4);
    float v[8] = {v0.x, v0.y, v0.z, v0.w, v1.x, v1.y, v1.z, v1.w};
    float mu = 0.f;
#pragma unroll
    for (int i = 0; i < 8; i++) mu += v[i];
    mu *= 0.125f;
    float var = 0.f;
#pragma unroll
    for (int i = 0; i < 8; i++) { float d = v[i] - mu; var += d * d; }
    var *= 0.125f;
    float inv = rsqrtf(var + 1e-5f);
    float* orow = out + (size_t)warp * 256;
#pragma unroll
    for (int i = 0; i < 8; i++)
        v[i] = elu_f((v[i] - mu) * inv * w[c0 + i] + b[c0 + i]);
    *(float4*)(orow + c0)     = make_float4(v[0], v[1], v[2], v[3]);
    *(float4*)(orow + c0 + 4) = make_float4(v[4], v[5], v[6], v[7]);
}

// =====================================================================
// Per-node attention projections on h = g_bufH.  One warp per node.
// =====================================================================
__global__ void node_dots_kernel(const float* __restrict__ a_src,
                                 const float* __restrict__ a_dst, int n)
{
    int warp = (blockIdx.x * blockDim.x + threadIdx.x) >> 5;
    int lane = threadIdx.x & 31;
    if (warp >= n) return;
    const float* row = g_bufH + (size_t)warp * 256;
    float s1 = 0.f, s2 = 0.f;
#pragma unroll
    for (int i = 0; i < 8; i++) {
        int c = lane + i * 32;
        float v = row[c];
        s1 += v * a_src[c];
        s2 += v * a_dst[c];
    }
#pragma unroll
    for (int o = 16; o; o >>= 1) {
        s1 += __shfl_down_sync(0xffffffff, s1, o);
        s2 += __shfl_down_sync(0xffffffff, s2, o);
    }
    if (lane == 0) { g_asrc[warp] = s1; g_adst[warp] = s2; }
}

// ------------------------- CSR build kernels --------------------------------
__global__ void zero_deg_kernel(int n)
{
    int i = blockIdx.x * blockDim.x + threadIdx.x;
    if (i < n) g_deg[i] = 0;
}

__global__ void hist_kernel(const void* __restrict__ ei, int E, int n)
{
    int t = blockIdx.x * blockDim.x + threadIdx.x;
    if (t >= E + n) return;
    int d = (t < E) ? edge_at(ei, (long long)E + t) : (t - E);
    if ((unsigned)d >= (unsigned)n) return;
    atomicAdd(&g_deg[d], 1);
}

// ---- parallel 3-phase scan ----
__global__ void scan1_kernel(int n)
{
    __shared__ int wsum[32];
    int tid = threadIdx.x;
    int i = blockIdx.x * 1024 + tid;
    int v = (i < n) ? g_deg[i] : 0;
    int s = v;
#pragma unroll
    for (int o = 16; o; o >>= 1) s += __shfl_down_sync(0xffffffff, s, o);
    if ((tid & 31) == 0) wsum[tid >> 5] = s;
    __syncthreads();
    if (tid < 32) {
        int t = wsum[tid];
#pragma unroll
        for (int o = 16; o; o >>= 1) t += __shfl_down_sync(0xffffffff, t, o);
        if (tid == 0) g_blksum[blockIdx.x] = t;
    }
}
__global__ void scan2_kernel(int nb)
{
    int tid = threadIdx.x;  // 64 threads
    int v = (tid < nb) ? g_blksum[tid] : 0;
    int x = v;
    __shared__ int sh[64];
    sh[tid] = v;
    __syncthreads();
    for (int o = 1; o < 64; o <<= 1) {
        int t = (tid >= o) ? sh[tid - o] : 0;
        __syncthreads();
        sh[tid] += t;
        __syncthreads();
    }
    if (tid < nb) g_blkoff[tid] = sh[tid] - x;  // exclusive
}
__global__ void scan3_kernel(int n)
{
    __shared__ int wsum[32];
    int tid = threadIdx.x;
    int lane = tid & 31, wid = tid >> 5;
    int i = blockIdx.x * 1024 + tid;
    int v = (i < n) ? g_deg[i] : 0;
    int x = v;
#pragma unroll
    for (int o = 1; o < 32; o <<= 1) {
        int t = __shfl_up_sync(0xffffffff, x, o);
        if (lane >= o) x += t;
    }
    if (lane == 31) wsum[wid] = x;
    __syncthreads();
    if (wid == 0) {
        int w = wsum[lane];
#pragma unroll
        for (int o = 1; o < 32; o <<= 1) {
            int t = __shfl_up_sync(0xffffffff, w, o);
            if (lane >= o) w += t;
        }
        wsum[lane] = w;
    }
    __syncthreads();
    int excl = x - v + (wid ? wsum[wid - 1] : 0) + g_blkoff[blockIdx.x];
    if (i < n) {
        g_off[i] = excl;
        g_cursor[i] = excl;
        if (i == n - 1) g_off[n] = excl + v;
    }
}

__global__ void scatter_kernel(const void* __restrict__ ei, int E, int n)
{
    int t = blockIdx.x * blockDim.x + threadIdx.x;
    if (t >= E + n) return;
    int s, d;
    if (t < E) {
        s = edge_at(ei, t);
        d = edge_at(ei, (long long)E + t);
    } else {
        s = t - E; d = t - E;
    }
    if ((unsigned)d >= (unsigned)n || (unsigned)s >= (unsigned)n) return;
    int p = atomicAdd(&g_cursor[d], 1);
    g_srcs[p] = s;
}

// =====================================================================
// GAT aggregation + fused GroupNorm(8)+ELU.  One block (256 thr) per
// node; thread t owns channel t; GN group = 8 consecutive lanes.
// =====================================================================
__global__ void gat_agg_kernel(const float* __restrict__ bias,
                               const float* __restrict__ gn_w,
                               const float* __restrict__ gn_b,
                               int out_id, int n)
{
    float* out = resolve_buf(out_id, nullptr);
    int node = blockIdx.x;
    int tid  = threadIdx.x;
    int s0 = g_off[node], s1 = g_off[node + 1];
    float ad = g_adst[node];

    __shared__ float red[256];

    float m = -1e30f;
    for (int j = s0 + tid; j < s1; j += 256) {
        float e = g_asrc[g_srcs[j]] + ad;
        e = (e > 0.f) ? e : 0.2f * e;
        m = fmaxf(m, e);
    }
    red[tid] = m;
    __syncthreads();
    for (int st = 128; st; st >>= 1) {
        if (tid < st) red[tid] = fmaxf(red[tid], red[tid + st]);
        __syncthreads();
    }
    m = red[0];
    __syncthreads();

    float s = 0.f;
    for (int j = s0 + tid; j < s1; j += 256) {
        float e = g_asrc[g_srcs[j]] + ad;
        e = (e > 0.f) ? e : 0.2f * e;
        s += expf(e - m);
    }
    red[tid] = s;
    __syncthreads();
    for (int st = 128; st; st >>= 1) {
        if (tid < st) red[tid] += red[tid + st];
        __syncthreads();
    }
    s = red[0];
    __syncthreads();
    float rinv = 1.0f / (s + 1e-16f);

    __shared__ float alpha_sh[128];
    __shared__ int   src_sh[128];
    float acc = 0.f;
    for (int base = s0; base < s1; base += 128) {
        int cnt = min(128, s1 - base);
        if (tid < cnt) {
            int sn = g_srcs[base + tid];
            src_sh[tid] = sn;
            float e = g_asrc[sn] + ad;
            e = (e > 0.f) ? e : 0.2f * e;
            alpha_sh[tid] = expf(e - m) * rinv;
        }
        __syncthreads();
        for (int j = 0; j < cnt; j++)
            acc += g_bufH[(size_t)src_sh[j] * 256 + tid] * alpha_sh[j];
        __syncthreads();
    }

    // fused GroupNorm(8)+ELU on (acc + bias)
    float o = acc + bias[tid];
    float su = o, sq = o * o;
    su += __shfl_xor_sync(0xffffffffu, su, 1);
    sq += __shfl_xor_sync(0xffffffffu, sq, 1);
    su += __shfl_xor_sync(0xffffffffu, su, 2);
    sq += __shfl_xor_sync(0xffffffffu, sq, 2);
    su += __shfl_xor_sync(0xffffffffu, su, 4);
    sq += __shfl_xor_sync(0xffffffffu, sq, 4);
    float mu = su * 0.125f;
    float iv = rsqrtf(sq * 0.125f - mu * mu + 1e-5f);
    float y = elu_f((o - mu) * iv * gn_w[tid] + gn_b[tid]);
    out[(size_t)node * 256 + tid] = y;
}

// ============================== launcher =====================================
extern "C" void kernel_launch(void* const* d_in, const int* in_sizes, int n_in,
                              void* d_out, int out_size)
{
    const float* x      = (const float*)d_in[0];
    const void*  ei     = d_in[1];
    const float* pre_w  = (const float*)d_in[2];
    const float* pre_b  = (const float*)d_in[3];
    const float* lin1_w = (const float*)d_in[4];
    const float* lin1_b = (const float*)d_in[5];
    const float* n1_w   = (const float*)d_in[6];
    const float* n1_b   = (const float*)d_in[7];
    const float* g1_w   = (const float*)d_in[8];
    const float* g1_as  = (const float*)d_in[9];
    const float* g1_ad  = (const float*)d_in[10];
    const float* g1_b   = (const float*)d_in[11];
    const float* n2_w   = (const float*)d_in[12];
    const float* n2_b   = (const float*)d_in[13];
    const float* g2_w   = (const float*)d_in[14];
    const float* g2_as  = (const float*)d_in[15];
    const float* g2_ad  = (const float*)d_in[16];
    const float* g2_b   = (const float*)d_in[17];
    const float* n3_w   = (const float*)d_in[18];
    const float* n3_b   = (const float*)d_in[19];
    const float* lin2_w = (const float*)d_in[20];
    const float* lin2_b = (const float*)d_in[21];
    const float* skip_w = (const float*)d_in[22];
    const float* skip_b = (const float*)d_in[23];
    float* out = (float*)d_out;

    int N = in_sizes[0] / CIN;
    int E = in_sizes[1] / 2;
    int ET = E + N;

    int warpBlocks = (N * 32 + 255) / 256;
    int eBlocks    = (ET + 255) / 256;
    int nBlocks    = (N + 255) / 256;
    int mBlocks    = (N + 127) / 128;
    int sBlocks    = (N + 1023) / 1024;

    // ---- edge dtype detection + CSR build; skip GEMM at slot 4 for ncu ----
    detect_dtype_kernel<<<1, 32>>>(ei, N);
    zero_deg_kernel<<<nBlocks, 256>>>(N);
    hist_kernel<<<eBlocks, 256>>>(ei, E, N);

    bfgemm_kernel<false, true, false><<<dim3(COUT / 128, mBlocks), 256>>>(
        BUF_EXT, x, skip_w, skip_b, nullptr, nullptr, BUF_EXT, out, N, COUT);

    scan1_kernel<<<sBlocks, 1024>>>(N);
    scan2_kernel<<<1, 64>>>(sBlocks);
    scan3_kernel<<<sBlocks, 1024>>>(N);
    scatter_kernel<<<eBlocks, 256>>>(ei, E, N);

    // ---- pre_norm + ELU : x -> bufA ----
    gnelu_kernel<<<warpBlocks, 256>>>(BUF_EXT, x, pre_w, pre_b, BUF_A, N);

    // ---- lin1 (+ fused GN1+ELU) : bufA -> bufB ----
    bfgemm_kernel<false, true, true><<<dim3(HDIM / 128, mBlocks), 256>>>(
        BUF_A, nullptr, lin1_w, lin1_b, n1_w, n1_b, BUF_B, nullptr, N, HDIM);

    // ---- GAT layer 1 : bufB -> (h=bufH) -> bufA (agg + fused GN2+ELU) ----
    bfgemm_kernel<false, false, false><<<dim3(HDIM / 128, mBlocks), 256>>>(
        BUF_B, nullptr, g1_w, nullptr, nullptr, nullptr, BUF_H, nullptr, N, HDIM);
    node_dots_kernel<<<warpBlocks, 256>>>(g1_as, g1_ad, N);
    gat_agg_kernel<<<N, 256>>>(g1_b, n2_w, n2_b, BUF_A, N);

    // ---- GAT layer 2 : bufA -> (h=bufH) -> bufB (agg + fused GN3+ELU) ----
    bfgemm_kernel<false, false, false><<<dim3(HDIM / 128, mBlocks), 256>>>(
        BUF_A, nullptr, g2_w, nullptr, nullptr, nullptr, BUF_H, nullptr, N, HDIM);
    node_dots_kernel<<<warpBlocks, 256>>>(g2_as, g2_ad, N);
    gat_agg_kernel<<<N, 256>>>(g2_b, n3_w, n3_b, BUF_B, N);

    // ---- lin2 accumulates into out (which already holds skip) ----
    bfgemm_kernel<true, true, false><<<dim3(COUT / 128, mBlocks), 256>>>(
        BUF_B, nullptr, lin2_w, lin2_b, nullptr, nullptr, BUF_EXT, out, N, COUT);
}

// round 15
// speedup vs baseline: 1.1727x; 1.1727x over previous
#include <cuda_runtime.h>
#include <cuda_bf16.h>
#include <math.h>
#include <stdint.h>

// ---------------- Problem-size constants (fixed by the dataset) -------------
#define NMAX   40000
#define EMAX   640000
#define ETMAX  (EMAX + NMAX)      // edges + self loops
#define CIN    256
#define HDIM   256
#define COUT   512
#define KDIM   256                // every single GEMM in this model has K = 256

// ---------------- Static device scratch (no allocation allowed) -------------
__device__ float g_bufA[(size_t)NMAX * HDIM];
__device__ float g_bufB[(size_t)NMAX * HDIM];
__device__ float g_bufH[(size_t)NMAX * HDIM];
__device__ float g_asrc[NMAX];
__device__ float g_adst[NMAX];
__device__ int   g_deg[NMAX];
__device__ int   g_off[NMAX + 1];
__device__ int   g_cursor[NMAX];
__device__ int   g_srcs[ETMAX];
__device__ int   g_is64;          // 1 if edge_index is int64, 0 if int32
__device__ int   g_blksum[64];
__device__ int   g_blkoff[64];

// Buffer-id resolution (device side).
#define BUF_A 0
#define BUF_B 1
#define BUF_H 2
#define BUF_EXT (-1)

__device__ __forceinline__ float* resolve_buf(int id, float* ext)
{
    switch (id) {
        case BUF_A: return g_bufA;
        case BUF_B: return g_bufB;
        case BUF_H: return g_bufH;
        default:    return ext;
    }
}
__device__ __forceinline__ const float* resolve_cbuf(int id, const float* ext)
{
    switch (id) {
        case BUF_A: return g_bufA;
        case BUF_B: return g_bufB;
        case BUF_H: return g_bufH;
        default:    return ext;
    }
}

// ---------------- bf16 helpers ----------------------------------------------
__device__ __forceinline__ void bf16_split(float a, __nv_bfloat16& hi, __nv_bfloat16& lo)
{
    hi = __float2bfloat16_rn(a);
    lo = __float2bfloat16_rn(a - __bfloat162float(hi));
}
__device__ __forceinline__ uint32_t pack_bf16(__nv_bfloat16 a, __nv_bfloat16 b)
{
    return (uint32_t)__bfloat16_as_ushort(a) | ((uint32_t)__bfloat16_as_ushort(b) << 16);
}

__device__ __forceinline__ void mma_bf16(float& c0, float& c1, float& c2, float& c3,
                                         uint32_t a0, uint32_t a1, uint32_t a2, uint32_t a3,
                                         uint32_t b0, uint32_t b1)
{
    asm volatile(
        "mma.sync.aligned.m16n8k16.row.col.f32.bf16.bf16.f32 "
        "{%0,%1,%2,%3}, {%4,%5,%6,%7}, {%8,%9}, {%0,%1,%2,%3};"
        : "+f"(c0), "+f"(c1), "+f"(c2), "+f"(c3)
        : "r"(a0), "r"(a1), "r"(a2), "r"(a3), "r"(b0), "r"(b1));
}

__device__ __forceinline__ float elu_f(float y)
{
    return (y > 0.f) ? y : expm1f(y);
}

// apply GroupNorm(8)+ELU to 8 consecutive floats held in registers
__device__ __forceinline__ void gn8_elu(float* v, const float* w, const float* b, int c0)
{
    float mu = 0.f;
#pragma unroll
    for (int i = 0; i < 8; i++) mu += v[i];
    mu *= 0.125f;
    float var = 0.f;
#pragma unroll
    for (int i = 0; i < 8; i++) { float d = v[i] - mu; var += d * d; }
    var *= 0.125f;
    float iv = rsqrtf(var + 1e-5f);
    float4 w0 = *(const float4*)(w + c0);
    float4 w1 = *(const float4*)(w + c0 + 4);
    float4 b0 = *(const float4*)(b + c0);
    float4 b1 = *(const float4*)(b + c0 + 4);
    float ww[8] = {w0.x, w0.y, w0.z, w0.w, w1.x, w1.y, w1.z, w1.w};
    float bb[8] = {b0.x, b0.y, b0.z, b0.w, b1.x, b1.y, b1.z, b1.w};
#pragma unroll
    for (int i = 0; i < 8; i++)
        v[i] = elu_f((v[i] - mu) * iv * ww[i] + bb[i]);
}

// =====================================================================
// 3-pass split-bf16 tensor-core GEMM:  C[m][j] = sum_k A[m][k]*W[j][k]
// Tile BM=128, BN=64, BK=16; 256 threads = 8 warps in 4(M) x 2(N);
// each warp computes 32x32 via 2x4 m16n8k16 fragments.
// Register prefetch + smem ping-pong => one __syncthreads per K-iter.
// GNA: fuse GroupNorm(8)+ELU onto the A operand (8 consecutive floats
//      per thread = exactly one group, all in-register).
// GNELU: fused GroupNorm(8)+ELU epilogue on the output.
// =====================================================================
#define SB32 12    // row stride in u32 (24 bf16 = 48B; (12r+q) mod 32 conflict-free)

template <bool BIAS, bool GNA, bool GNELU>
__global__ void __launch_bounds__(256)
bfgemm_kernel(int A_id, const float* __restrict__ A_ext,
              const float* __restrict__ W,
              const float* __restrict__ bias,
              const float* __restrict__ gnA_w,
              const float* __restrict__ gnA_b,
              const float* __restrict__ gn_w,
              const float* __restrict__ gn_b,
              int C_id, float* __restrict__ C_ext,
              int Nrows, int J)
{
    const float* A = resolve_cbuf(A_id, A_ext);
    float* C = resolve_buf(C_id, C_ext);

    __shared__ uint32_t As_hi[2][128 * SB32];
    __shared__ uint32_t As_lo[2][128 * SB32];
    __shared__ uint32_t Bs_hi[2][64 * SB32];
    __shared__ uint32_t Bs_lo[2][64 * SB32];

    int tid  = threadIdx.x;
    int wid  = tid >> 5;
    int lane = tid & 31;
    int grp  = lane >> 2;      // 0..7
    int qid  = lane & 3;       // 0..3

    int m0 = blockIdx.y * 128;
    int j0 = blockIdx.x * 64;

    int wm = (wid >> 1) * 32;  // warp M slab
    int wn = (wid & 1) * 32;   // warp N slab

    float acc[2][4][4];
#pragma unroll
    for (int i = 0; i < 2; i++)
#pragma unroll
        for (int j = 0; j < 4; j++)
#pragma unroll
            for (int q = 0; q < 4; q++) acc[i][j][q] = 0.f;

    // loader mapping
    int a_row  = tid >> 1;         // 0..127
    int a_half = tid & 1;          // k offset 0 / 8
    int b_row  = tid >> 2;         // 0..63
    int b_q    = tid & 3;          // k offset 0,4,8,12
    int a_grow = m0 + a_row;
    bool a_ok  = (a_grow < Nrows);
    const float* aptr = A + (size_t)a_grow * KDIM + a_half * 8;
    const float* bptr = W + (size_t)(j0 + b_row) * KDIM + b_q * 4;

    uint32_t a_st = a_row * SB32 + a_half * 4;
    uint32_t b_st = b_row * SB32 + b_q * 2;

    // prefetch chunk 0
    float4 av0, av1, bv;
    av0 = a_ok ? *(const float4*)(aptr)     : make_float4(0.f, 0.f, 0.f, 0.f);
    av1 = a_ok ? *(const float4*)(aptr + 4) : make_float4(0.f, 0.f, 0.f, 0.f);
    bv  = *(const float4*)(bptr);

    for (int it = 0; it < 16; it++) {
        int pp = it & 1;
        // ---- convert + store current chunk into ping-pong slot ----
        {
            float va[8] = {av0.x, av0.y, av0.z, av0.w, av1.x, av1.y, av1.z, av1.w};
            if (GNA) gn8_elu(va, gnA_w, gnA_b, it * 16 + a_half * 8);
            uint32_t wh[4], wl[4];
#pragma unroll
            for (int i = 0; i < 4; i++) {
                __nv_bfloat16 h0, l0, h1, l1;
                bf16_split(va[2 * i],     h0, l0);
                bf16_split(va[2 * i + 1], h1, l1);
                wh[i] = pack_bf16(h0, h1);
                wl[i] = pack_bf16(l0, l1);
            }
            *(uint4*)(As_hi[pp] + a_st) = make_uint4(wh[0], wh[1], wh[2], wh[3]);
            *(uint4*)(As_lo[pp] + a_st) = make_uint4(wl[0], wl[1], wl[2], wl[3]);

            float vb[4] = {bv.x, bv.y, bv.z, bv.w};
            __nv_bfloat16 h0, l0, h1, l1;
            bf16_split(vb[0], h0, l0); bf16_split(vb[1], h1, l1);
            uint32_t bh0 = pack_bf16(h0, h1), bl0 = pack_bf16(l0, l1);
            bf16_split(vb[2], h0, l0); bf16_split(vb[3], h1, l1);
            uint32_t bh1 = pack_bf16(h0, h1), bl1 = pack_bf16(l0, l1);
            *(uint2*)(Bs_hi[pp] + b_st) = make_uint2(bh0, bh1);
            *(uint2*)(Bs_lo[pp] + b_st) = make_uint2(bl0, bl1);
        }

        // ---- prefetch next chunk ----
        if (it < 15) {
            int k0 = (it + 1) * 16;
            av0 = a_ok ? *(const float4*)(aptr + k0)     : make_float4(0.f, 0.f, 0.f, 0.f);
            av1 = a_ok ? *(const float4*)(aptr + k0 + 4) : make_float4(0.f, 0.f, 0.f, 0.f);
            bv  = *(const float4*)(bptr + k0);
        }

        __syncthreads();   // single barrier per iter (ping-pong protects reuse)

        // ---- fragment loads + MMA ----
        uint32_t ah[2][4], al[2][4];
#pragma unroll
        for (int mt = 0; mt < 2; mt++) {
            int r0 = (wm + mt * 16 + grp) * SB32 + qid;
            int r1 = r0 + 8 * SB32;
            ah[mt][0] = As_hi[pp][r0];     ah[mt][1] = As_hi[pp][r1];
            ah[mt][2] = As_hi[pp][r0 + 4]; ah[mt][3] = As_hi[pp][r1 + 4];
            al[mt][0] = As_lo[pp][r0];     al[mt][1] = As_lo[pp][r1];
            al[mt][2] = As_lo[pp][r0 + 4]; al[mt][3] = As_lo[pp][r1 + 4];
        }
        uint32_t bh[4][2], bl[4][2];
#pragma unroll
        for (int nt = 0; nt < 4; nt++) {
            int rb = (wn + nt * 8 + grp) * SB32 + qid;
            bh[nt][0] = Bs_hi[pp][rb]; bh[nt][1] = Bs_hi[pp][rb + 4];
            bl[nt][0] = Bs_lo[pp][rb]; bl[nt][1] = Bs_lo[pp][rb + 4];
        }
#pragma unroll
        for (int mt = 0; mt < 2; mt++) {
#pragma unroll
            for (int nt = 0; nt < 4; nt++) {
                float* c = acc[mt][nt];
                mma_bf16(c[0], c[1], c[2], c[3],
                         ah[mt][0], ah[mt][1], ah[mt][2], ah[mt][3],
                         bh[nt][0], bh[nt][1]);
                mma_bf16(c[0], c[1], c[2], c[3],
                         ah[mt][0], ah[mt][1], ah[mt][2], ah[mt][3],
                         bl[nt][0], bl[nt][1]);
                mma_bf16(c[0], c[1], c[2], c[3],
                         al[mt][0], al[mt][1], al[mt][2], al[mt][3],
                         bh[nt][0], bh[nt][1]);
            }
        }
    }

    // ---- epilogue (optionally fused GroupNorm(8)+ELU) ----
#pragma unroll
    for (int mt = 0; mt < 2; mt++) {
        int row0 = m0 + wm + mt * 16 + grp;
        int row1 = row0 + 8;
#pragma unroll
        for (int nt = 0; nt < 4; nt++) {
            int col = j0 + wn + nt * 8 + qid * 2;
            float b0 = 0.f, b1 = 0.f;
            if (BIAS) { b0 = bias[col]; b1 = bias[col + 1]; }
            float v0 = acc[mt][nt][0] + b0;
            float v1 = acc[mt][nt][1] + b1;
            float v2 = acc[mt][nt][2] + b0;
            float v3 = acc[mt][nt][3] + b1;
            if (GNELU) {
                float s01 = v0 + v1, q01 = v0 * v0 + v1 * v1;
                float s23 = v2 + v3, q23 = v2 * v2 + v3 * v3;
                s01 += __shfl_xor_sync(0xffffffffu, s01, 1);
                q01 += __shfl_xor_sync(0xffffffffu, q01, 1);
                s23 += __shfl_xor_sync(0xffffffffu, s23, 1);
                q23 += __shfl_xor_sync(0xffffffffu, q23, 1);
                s01 += __shfl_xor_sync(0xffffffffu, s01, 2);
                q01 += __shfl_xor_sync(0xffffffffu, q01, 2);
                s23 += __shfl_xor_sync(0xffffffffu, s23, 2);
                q23 += __shfl_xor_sync(0xffffffffu, q23, 2);
                float mu0 = s01 * 0.125f;
                float iv0 = rsqrtf(q01 * 0.125f - mu0 * mu0 + 1e-5f);
                float mu1 = s23 * 0.125f;
                float iv1 = rsqrtf(q23 * 0.125f - mu1 * mu1 + 1e-5f);
                float w0 = gn_w[col], w1 = gn_w[col + 1];
                float gb0 = gn_b[col], gb1 = gn_b[col + 1];
                v0 = elu_f((v0 - mu0) * iv0 * w0 + gb0);
                v1 = elu_f((v1 - mu0) * iv0 * w1 + gb1);
                v2 = elu_f((v2 - mu1) * iv1 * w0 + gb0);
                v3 = elu_f((v3 - mu1) * iv1 * w1 + gb1);
            }
            if (row0 < Nrows) {
                float* p = C + (size_t)row0 * J + col;
                p[0] = v0; p[1] = v1;
            }
            if (row1 < Nrows) {
                float* p = C + (size_t)row1 * J + col;
                p[0] = v2; p[1] = v3;
            }
        }
    }
}

// =====================================================================
// Dual GEMM (lin2 + skip fused):  out[m][j] = bufB[m]·lin2_w[j]
//                                           + x[m]·skip_w[j] + biases
// Same tile as bfgemm, K total 512 (32 iters: first 16 from bufB/lin2_w,
// last 16 from x/skip_w).
// =====================================================================
__global__ void __launch_bounds__(256)
dualgemm_kernel(const float* __restrict__ x,
                const float* __restrict__ w1,   // lin2_w [512,256]
                const float* __restrict__ w2,   // skip_w [512,256]
                const float* __restrict__ b1,
                const float* __restrict__ b2,
                float* __restrict__ C,
                int Nrows, int J)
{
    __shared__ uint32_t As_hi[2][128 * SB32];
    __shared__ uint32_t As_lo[2][128 * SB32];
    __shared__ uint32_t Bs_hi[2][64 * SB32];
    __shared__ uint32_t Bs_lo[2][64 * SB32];

    int tid  = threadIdx.x;
    int wid  = tid >> 5;
    int lane = tid & 31;
    int grp  = lane >> 2;
    int qid  = lane & 3;

    int m0 = blockIdx.y * 128;
    int j0 = blockIdx.x * 64;
    int wm = (wid >> 1) * 32;
    int wn = (wid & 1) * 32;

    float acc[2][4][4];
#pragma unroll
    for (int i = 0; i < 2; i++)
#pragma unroll
        for (int j = 0; j < 4; j++)
#pragma unroll
            for (int q = 0; q < 4; q++) acc[i][j][q] = 0.f;

    int a_row  = tid >> 1;
    int a_half = tid & 1;
    int b_row  = tid >> 2;
    int b_q    = tid & 3;
    int a_grow = m0 + a_row;
    bool a_ok  = (a_grow < Nrows);
    const float* aptr1 = g_bufB + (size_t)a_grow * KDIM + a_half * 8;
    const float* aptr2 = x      + (size_t)a_grow * KDIM + a_half * 8;
    const float* bptr1 = w1 + (size_t)(j0 + b_row) * KDIM + b_q * 4;
    const float* bptr2 = w2 + (size_t)(j0 + b_row) * KDIM + b_q * 4;

    uint32_t a_st = a_row * SB32 + a_half * 4;
    uint32_t b_st = b_row * SB32 + b_q * 2;

    float4 av0, av1, bv;
    av0 = a_ok ? *(const float4*)(aptr1)     : make_float4(0.f, 0.f, 0.f, 0.f);
    av1 = a_ok ? *(const float4*)(aptr1 + 4) : make_float4(0.f, 0.f, 0.f, 0.f);
    bv  = *(const float4*)(bptr1);

    for (int it = 0; it < 32; it++) {
        int pp = it & 1;
        {
            float va[8] = {av0.x, av0.y, av0.z, av0.w, av1.x, av1.y, av1.z, av1.w};
            uint32_t wh[4], wl[4];
#pragma unroll
            for (int i = 0; i < 4; i++) {
                __nv_bfloat16 h0, l0, h1, l1;
                bf16_split(va[2 * i],     h0, l0);
                bf16_split(va[2 * i + 1], h1, l1);
                wh[i] = pack_bf16(h0, h1);
                wl[i] = pack_bf16(l0, l1);
            }
            *(uint4*)(As_hi[pp] + a_st) = make_uint4(wh[0], wh[1], wh[2], wh[3]);
            *(uint4*)(As_lo[pp] + a_st) = make_uint4(wl[0], wl[1], wl[2], wl[3]);

            float vb[4] = {bv.x, bv.y, bv.z, bv.w};
            __nv_bfloat16 h0, l0, h1, l1;
            bf16_split(vb[0], h0, l0); bf16_split(vb[1], h1, l1);
            uint32_t bh0 = pack_bf16(h0, h1), bl0 = pack_bf16(l0, l1);
            bf16_split(vb[2], h0, l0); bf16_split(vb[3], h1, l1);
            uint32_t bh1 = pack_bf16(h0, h1), bl1 = pack_bf16(l0, l1);
            *(uint2*)(Bs_hi[pp] + b_st) = make_uint2(bh0, bh1);
            *(uint2*)(Bs_lo[pp] + b_st) = make_uint2(bl0, bl1);
        }

        if (it < 31) {
            int nit = it + 1;
            int k0 = (nit & 15) * 16;
            const float* ap = (nit < 16) ? aptr1 : aptr2;
            const float* bp = (nit < 16) ? bptr1 : bptr2;
            av0 = a_ok ? *(const float4*)(ap + k0)     : make_float4(0.f, 0.f, 0.f, 0.f);
            av1 = a_ok ? *(const float4*)(ap + k0 + 4) : make_float4(0.f, 0.f, 0.f, 0.f);
            bv  = *(const float4*)(bp + k0);
        }

        __syncthreads();

        uint32_t ah[2][4], al[2][4];
#pragma unroll
        for (int mt = 0; mt < 2; mt++) {
            int r0 = (wm + mt * 16 + grp) * SB32 + qid;
            int r1 = r0 + 8 * SB32;
            ah[mt][0] = As_hi[pp][r0];     ah[mt][1] = As_hi[pp][r1];
            ah[mt][2] = As_hi[pp][r0 + 4]; ah[mt][3] = As_hi[pp][r1 + 4];
            al[mt][0] = As_lo[pp][r0];     al[mt][1] = As_lo[pp][r1];
            al[mt][2] = As_lo[pp][r0 + 4]; al[mt][3] = As_lo[pp][r1 + 4];
        }
        uint32_t bh[4][2], bl[4][2];
#pragma unroll
        for (int nt = 0; nt < 4; nt++) {
            int rb = (wn + nt * 8 + grp) * SB32 + qid;
            bh[nt][0] = Bs_hi[pp][rb]; bh[nt][1] = Bs_hi[pp][rb + 4];
            bl[nt][0] = Bs_lo[pp][rb]; bl[nt][1] = Bs_lo[pp][rb + 4];
        }
#pragma unroll
        for (int mt = 0; mt < 2; mt++) {
#pragma unroll
            for (int nt = 0; nt < 4; nt++) {
                float* c = acc[mt][nt];
                mma_bf16(c[0], c[1], c[2], c[3],
                         ah[mt][0], ah[mt][1], ah[mt][2], ah[mt][3],
                         bh[nt][0], bh[nt][1]);
                mma_bf16(c[0], c[1], c[2], c[3],
                         ah[mt][0], ah[mt][1], ah[mt][2], ah[mt][3],
                         bl[nt][0], bl[nt][1]);
                mma_bf16(c[0], c[1], c[2], c[3],
                         al[mt][0], al[mt][1], al[mt][2], al[mt][3],
                         bh[nt][0], bh[nt][1]);
            }
        }
    }

#pragma unroll
    for (int mt = 0; mt < 2; mt++) {
        int row0 = m0 + wm + mt * 16 + grp;
        int row1 = row0 + 8;
#pragma unroll
        for (int nt = 0; nt < 4; nt++) {
            int col = j0 + wn + nt * 8 + qid * 2;
            float b0 = b1[col] + b2[col];
            float bb1 = b1[col + 1] + b2[col + 1];
            if (row0 < Nrows) {
                float* p = C + (size_t)row0 * J + col;
                p[0] = acc[mt][nt][0] + b0;
                p[1] = acc[mt][nt][1] + bb1;
            }
            if (row1 < Nrows) {
                float* p = C + (size_t)row1 * J + col;
                p[0] = acc[mt][nt][2] + b0;
                p[1] = acc[mt][nt][3] + bb1;
            }
        }
    }
}

// Read edge endpoint idx (0..2E-1 flattened) honoring detected dtype.
__device__ __forceinline__ int edge_at(const void* ei, long long flat)
{
    if (g_is64) return (int)((const long long*)ei)[flat];
    return ((const int*)ei)[flat];
}

__global__ void detect_dtype_kernel(const void* ei, int n)
{
    if (threadIdx.x == 0 && blockIdx.x == 0) {
        const long long* p = (const long long*)ei;
        int ok = 1;
        for (int i = 0; i < 64; i++) {
            long long v = p[i];
            if (v < 0 || v >= n) { ok = 0; break; }
        }
        g_is64 = ok;
    }
}

// =====================================================================
// Per-node attention projections on h = g_bufH.  One warp per node.
// =====================================================================
__global__ void node_dots_kernel(const float* __restrict__ a_src,
                                 const float* __restrict__ a_dst, int n)
{
    int warp = (blockIdx.x * blockDim.x + threadIdx.x) >> 5;
    int lane = threadIdx.x & 31;
    if (warp >= n) return;
    const float* row = g_bufH + (size_t)warp * 256;
    float s1 = 0.f, s2 = 0.f;
#pragma unroll
    for (int i = 0; i < 8; i++) {
        int c = lane + i * 32;
        float v = row[c];
        s1 += v * a_src[c];
        s2 += v * a_dst[c];
    }
#pragma unroll
    for (int o = 16; o; o >>= 1) {
        s1 += __shfl_down_sync(0xffffffff, s1, o);
        s2 += __shfl_down_sync(0xffffffff, s2, o);
    }
    if (lane == 0) { g_asrc[warp] = s1; g_adst[warp] = s2; }
}

// ------------------------- CSR build kernels --------------------------------
__global__ void zero_deg_kernel(int n)
{
    int i = blockIdx.x * blockDim.x + threadIdx.x;
    if (i < n) g_deg[i] = 0;
}

__global__ void hist_kernel(const void* __restrict__ ei, int E, int n)
{
    int t = blockIdx.x * blockDim.x + threadIdx.x;
    if (t >= E + n) return;
    int d = (t < E) ? edge_at(ei, (long long)E + t) : (t - E);
    if ((unsigned)d >= (unsigned)n) return;
    atomicAdd(&g_deg[d], 1);
}

// ---- parallel 3-phase scan ----
__global__ void scan1_kernel(int n)
{
    __shared__ int wsum[32];
    int tid = threadIdx.x;
    int i = blockIdx.x * 1024 + tid;
    int v = (i < n) ? g_deg[i] : 0;
    int s = v;
#pragma unroll
    for (int o = 16; o; o >>= 1) s += __shfl_down_sync(0xffffffff, s, o);
    if ((tid & 31) == 0) wsum[tid >> 5] = s;
    __syncthreads();
    if (tid < 32) {
        int t = wsum[tid];
#pragma unroll
        for (int o = 16; o; o >>= 1) t += __shfl_down_sync(0xffffffff, t, o);
        if (tid == 0) g_blksum[blockIdx.x] = t;
    }
}
__global__ void scan2_kernel(int nb)
{
    int tid = threadIdx.x;  // 64 threads
    int v = (tid < nb) ? g_blksum[tid] : 0;
    int x = v;
    __shared__ int sh[64];
    sh[tid] = v;
    __syncthreads();
    for (int o = 1; o < 64; o <<= 1) {
        int t = (tid >= o) ? sh[tid - o] : 0;
        __syncthreads();
        sh[tid] += t;
        __syncthreads();
    }
    if (tid < nb) g_blkoff[tid] = sh[tid] - x;  // exclusive
}
__global__ void scan3_kernel(int n)
{
    __shared__ int wsum[32];
    int tid = threadIdx.x;
    int lane = tid & 31, wid = tid >> 5;
    int i = blockIdx.x * 1024 + tid;
    int v = (i < n) ? g_deg[i] : 0;
    int x = v;
#pragma unroll
    for (int o = 1; o < 32; o <<= 1) {
        int t = __shfl_up_sync(0xffffffff, x, o);
        if (lane >= o) x += t;
    }
    if (lane == 31) wsum[wid] = x;
    __syncthreads();
    if (wid == 0) {
        int w = wsum[lane];
#pragma unroll
        for (int o = 1; o < 32; o <<= 1) {
            int t = __shfl_up_sync(0xffffffff, w, o);
            if (lane >= o) w += t;
        }
        wsum[lane] = w;
    }
    __syncthreads();
    int excl = x - v + (wid ? wsum[wid - 1] : 0) + g_blkoff[blockIdx.x];
    if (i < n) {
        g_off[i] = excl;
        g_cursor[i] = excl;
        if (i == n - 1) g_off[n] = excl + v;
    }
}

__global__ void scatter_kernel(const void* __restrict__ ei, int E, int n)
{
    int t = blockIdx.x * blockDim.x + threadIdx.x;
    if (t >= E + n) return;
    int s, d;
    if (t < E) {
        s = edge_at(ei, t);
        d = edge_at(ei, (long long)E + t);
    } else {
        s = t - E; d = t - E;
    }
    if ((unsigned)d >= (unsigned)n || (unsigned)s >= (unsigned)n) return;
    int p = atomicAdd(&g_cursor[d], 1);
    g_srcs[p] = s;
}

// =====================================================================
// GAT aggregation + fused GroupNorm(8)+ELU.  One block (256 thr) per
// node; thread t owns channel t; GN group = 8 consecutive lanes.
// =====================================================================
__global__ void gat_agg_kernel(const float* __restrict__ bias,
                               const float* __restrict__ gn_w,
                               const float* __restrict__ gn_b,
                               int out_id, int n)
{
    float* out = resolve_buf(out_id, nullptr);
    int node = blockIdx.x;
    int tid  = threadIdx.x;
    int s0 = g_off[node], s1 = g_off[node + 1];
    float ad = g_adst[node];

    __shared__ float red[256];

    float m = -1e30f;
    for (int j = s0 + tid; j < s1; j += 256) {
        float e = g_asrc[g_srcs[j]] + ad;
        e = (e > 0.f) ? e : 0.2f * e;
        m = fmaxf(m, e);
    }
    red[tid] = m;
    __syncthreads();
    for (int st = 128; st; st >>= 1) {
        if (tid < st) red[tid] = fmaxf(red[tid], red[tid + st]);
        __syncthreads();
    }
    m = red[0];
    __syncthreads();

    float s = 0.f;
    for (int j = s0 + tid; j < s1; j += 256) {
        float e = g_asrc[g_srcs[j]] + ad;
        e = (e > 0.f) ? e : 0.2f * e;
        s += expf(e - m);
    }
    red[tid] = s;
    __syncthreads();
    for (int st = 128; st; st >>= 1) {
        if (tid < st) red[tid] += red[tid + st];
        __syncthreads();
    }
    s = red[0];
    __syncthreads();
    float rinv = 1.0f / (s + 1e-16f);

    __shared__ float alpha_sh[128];
    __shared__ int   src_sh[128];
    float acc = 0.f;
    for (int base = s0; base < s1; base += 128) {
        int cnt = min(128, s1 - base);
        if (tid < cnt) {
            int sn = g_srcs[base + tid];
            src_sh[tid] = sn;
            float e = g_asrc[sn] + ad;
            e = (e > 0.f) ? e : 0.2f * e;
            alpha_sh[tid] = expf(e - m) * rinv;
        }
        __syncthreads();
        for (int j = 0; j < cnt; j++)
            acc += g_bufH[(size_t)src_sh[j] * 256 + tid] * alpha_sh[j];
        __syncthreads();
    }

    // fused GroupNorm(8)+ELU on (acc + bias)
    float o = acc + bias[tid];
    float su = o, sq = o * o;
    su += __shfl_xor_sync(0xffffffffu, su, 1);
    sq += __shfl_xor_sync(0xffffffffu, sq, 1);
    su += __shfl_xor_sync(0xffffffffu, su, 2);
    sq += __shfl_xor_sync(0xffffffffu, sq, 2);
    su += __shfl_xor_sync(0xffffffffu, su, 4);
    sq += __shfl_xor_sync(0xffffffffu, sq, 4);
    float mu = su * 0.125f;
    float iv = rsqrtf(sq * 0.125f - mu * mu + 1e-5f);
    float y = elu_f((o - mu) * iv * gn_w[tid] + gn_b[tid]);
    out[(size_t)node * 256 + tid] = y;
}

// ============================== launcher =====================================
extern "C" void kernel_launch(void* const* d_in, const int* in_sizes, int n_in,
                              void* d_out, int out_size)
{
    const float* x      = (const float*)d_in[0];
    const void*  ei     = d_in[1];
    const float* pre_w  = (const float*)d_in[2];
    const float* pre_b  = (const float*)d_in[3];
    const float* lin1_w = (const float*)d_in[4];
    const float* lin1_b = (const float*)d_in[5];
    const float* n1_w   = (const float*)d_in[6];
    const float* n1_b   = (const float*)d_in[7];
    const float* g1_w   = (const float*)d_in[8];
    const float* g1_as  = (const float*)d_in[9];
    const float* g1_ad  = (const float*)d_in[10];
    const float* g1_b   = (const float*)d_in[11];
    const float* n2_w   = (const float*)d_in[12];
    const float* n2_b   = (const float*)d_in[13];
    const float* g2_w   = (const float*)d_in[14];
    const float* g2_as  = (const float*)d_in[15];
    const float* g2_ad  = (const float*)d_in[16];
    const float* g2_b   = (const float*)d_in[17];
    const float* n3_w   = (const float*)d_in[18];
    const float* n3_b   = (const float*)d_in[19];
    const float* lin2_w = (const float*)d_in[20];
    const float* lin2_b = (const float*)d_in[21];
    const float* skip_w = (const float*)d_in[22];
    const float* skip_b = (const float*)d_in[23];
    float* out = (float*)d_out;

    int N = in_sizes[0] / CIN;
    int E = in_sizes[1] / 2;
    int ET = E + N;

    int warpBlocks = (N * 32 + 255) / 256;
    int eBlocks    = (ET + 255) / 256;
    int nBlocks    = (N + 255) / 256;
    int mBlocks    = (N + 127) / 128;
    int sBlocks    = (N + 1023) / 1024;

    // ---- CSR build start; lin1 GEMM is the 6th launch (ncu profile) ----
    detect_dtype_kernel<<<1, 32>>>(ei, N);
    zero_deg_kernel<<<nBlocks, 256>>>(N);
    hist_kernel<<<eBlocks, 256>>>(ei, E, N);
    scan1_kernel<<<sBlocks, 1024>>>(N);
    scan2_kernel<<<1, 64>>>(sBlocks);

    // ---- lin1: x --(fused pre_norm GN+ELU on A)--> GEMM --(fused GN1+ELU)--> bufB
    bfgemm_kernel<true, true, true><<<dim3(HDIM / 64, mBlocks), 256>>>(
        BUF_EXT, x, lin1_w, lin1_b, pre_w, pre_b, n1_w, n1_b,
        BUF_B, nullptr, N, HDIM);

    scan3_kernel<<<sBlocks, 1024>>>(N);
    scatter_kernel<<<eBlocks, 256>>>(ei, E, N);

    // ---- GAT layer 1 : bufB -> (h=bufH) -> bufA (agg + fused GN2+ELU) ----
    bfgemm_kernel<false, false, false><<<dim3(HDIM / 64, mBlocks), 256>>>(
        BUF_B, nullptr, g1_w, nullptr, nullptr, nullptr, nullptr, nullptr,
        BUF_H, nullptr, N, HDIM);
    node_dots_kernel<<<warpBlocks, 256>>>(g1_as, g1_ad, N);
    gat_agg_kernel<<<N, 256>>>(g1_b, n2_w, n2_b, BUF_A, N);

    // ---- GAT layer 2 : bufA -> (h=bufH) -> bufB (agg + fused GN3+ELU) ----
    bfgemm_kernel<false, false, false><<<dim3(HDIM / 64, mBlocks), 256>>>(
        BUF_A, nullptr, g2_w, nullptr, nullptr, nullptr, nullptr, nullptr,
        BUF_H, nullptr, N, HDIM);
    node_dots_kernel<<<warpBlocks, 256>>>(g2_as, g2_ad, N);
    gat_agg_kernel<<<N, 256>>>(g2_b, n3_w, n3_b, BUF_B, N);

    // ---- fused lin2 + skip -> out (single pass, no ACC read) ----
    dualgemm_kernel<<<dim3(COUT / 64, mBlocks), 256>>>(
        x, lin2_w, skip_w, lin2_b, skip_b, out, N, COUT);
}

// round 16
// speedup vs baseline: 1.5188x; 1.2952x over previous
#include <cuda_runtime.h>
#include <cuda_bf16.h>
#include <math.h>
#include <stdint.h>

// ---------------- Problem-size constants (fixed by the dataset) -------------
#define NMAX   40000
#define EMAX   640000
#define ETMAX  (EMAX + NMAX)      // edges + self loops
#define CIN    256
#define HDIM   256
#define COUT   512
#define KDIM   256                // every single GEMM in this model has K = 256

// ---------------- Static device scratch (no allocation allowed) -------------
__device__ float g_bufA[(size_t)NMAX * HDIM];
__device__ float g_bufB[(size_t)NMAX * HDIM];
__device__ float g_bufH[(size_t)NMAX * HDIM];
__device__ float g_asrc[NMAX];
__device__ float g_adst[NMAX];
__device__ int   g_deg[NMAX];
__device__ int   g_off[NMAX + 1];
__device__ int   g_cursor[NMAX];
__device__ int   g_srcs[ETMAX];
__device__ int   g_is64;          // 1 if edge_index is int64, 0 if int32
__device__ int   g_blksum[64];
__device__ int   g_blkoff[64];

// Buffer-id resolution (device side).
#define BUF_A 0
#define BUF_B 1
#define BUF_H 2
#define BUF_EXT (-1)

__device__ __forceinline__ float* resolve_buf(int id, float* ext)
{
    switch (id) {
        case BUF_A: return g_bufA;
        case BUF_B: return g_bufB;
        case BUF_H: return g_bufH;
        default:    return ext;
    }
}
__device__ __forceinline__ const float* resolve_cbuf(int id, const float* ext)
{
    switch (id) {
        case BUF_A: return g_bufA;
        case BUF_B: return g_bufB;
        case BUF_H: return g_bufH;
        default:    return ext;
    }
}

// ---------------- bf16 helpers ----------------------------------------------
__device__ __forceinline__ void bf16_split(float a, __nv_bfloat16& hi, __nv_bfloat16& lo)
{
    hi = __float2bfloat16_rn(a);
    lo = __float2bfloat16_rn(a - __bfloat162float(hi));
}
__device__ __forceinline__ uint32_t pack_bf16(__nv_bfloat16 a, __nv_bfloat16 b)
{
    return (uint32_t)__bfloat16_as_ushort(a) | ((uint32_t)__bfloat16_as_ushort(b) << 16);
}

__device__ __forceinline__ void mma_bf16(float& c0, float& c1, float& c2, float& c3,
                                         uint32_t a0, uint32_t a1, uint32_t a2, uint32_t a3,
                                         uint32_t b0, uint32_t b1)
{
    asm volatile(
        "mma.sync.aligned.m16n8k16.row.col.f32.bf16.bf16.f32 "
        "{%0,%1,%2,%3}, {%4,%5,%6,%7}, {%8,%9}, {%0,%1,%2,%3};"
        : "+f"(c0), "+f"(c1), "+f"(c2), "+f"(c3)
        : "r"(a0), "r"(a1), "r"(a2), "r"(a3), "r"(b0), "r"(b1));
}

__device__ __forceinline__ float elu_f(float y)
{
    return (y > 0.f) ? y : expm1f(y);
}

// apply GroupNorm(8)+ELU to 8 consecutive floats held in registers
__device__ __forceinline__ void gn8_elu(float* v, const float* w, const float* b, int c0)
{
    float mu = 0.f;
#pragma unroll
    for (int i = 0; i < 8; i++) mu += v[i];
    mu *= 0.125f;
    float var = 0.f;
#pragma unroll
    for (int i = 0; i < 8; i++) { float d = v[i] - mu; var += d * d; }
    var *= 0.125f;
    float iv = rsqrtf(var + 1e-5f);
    float4 w0 = *(const float4*)(w + c0);
    float4 w1 = *(const float4*)(w + c0 + 4);
    float4 b0 = *(const float4*)(b + c0);
    float4 b1 = *(const float4*)(b + c0 + 4);
    float ww[8] = {w0.x, w0.y, w0.z, w0.w, w1.x, w1.y, w1.z, w1.w};
    float bb[8] = {b0.x, b0.y, b0.z, b0.w, b1.x, b1.y, b1.z, b1.w};
#pragma unroll
    for (int i = 0; i < 8; i++)
        v[i] = elu_f((v[i] - mu) * iv * ww[i] + bb[i]);
}

// =====================================================================
// 3-pass split-bf16 tensor-core GEMM:  C[m][j] = sum_k A[m][k]*W[j][k]
// Tile BM=128, BN=64, BK=16; 256 threads = 8 warps in 4(M) x 2(N);
// each warp computes 32x32 via 2x4 m16n8k16 fragments.
// Register prefetch + smem ping-pong => one __syncthreads per K-iter.
// GNA: fuse GroupNorm(8)+ELU onto the A operand.
// GNELU: fused GroupNorm(8)+ELU epilogue on the output.
// =====================================================================
#define SB32 12    // row stride in u32 (24 bf16 = 48B; (12r+q) mod 32 conflict-free)

template <bool BIAS, bool GNA, bool GNELU>
__global__ void __launch_bounds__(256)
bfgemm_kernel(int A_id, const float* __restrict__ A_ext,
              const float* __restrict__ W,
              const float* __restrict__ bias,
              const float* __restrict__ gnA_w,
              const float* __restrict__ gnA_b,
              const float* __restrict__ gn_w,
              const float* __restrict__ gn_b,
              int C_id, float* __restrict__ C_ext,
              int Nrows, int J)
{
    const float* A = resolve_cbuf(A_id, A_ext);
    float* C = resolve_buf(C_id, C_ext);

    __shared__ uint32_t As_hi[2][128 * SB32];
    __shared__ uint32_t As_lo[2][128 * SB32];
    __shared__ uint32_t Bs_hi[2][64 * SB32];
    __shared__ uint32_t Bs_lo[2][64 * SB32];

    int tid  = threadIdx.x;
    int wid  = tid >> 5;
    int lane = tid & 31;
    int grp  = lane >> 2;      // 0..7
    int qid  = lane & 3;       // 0..3

    int m0 = blockIdx.y * 128;
    int j0 = blockIdx.x * 64;

    int wm = (wid >> 1) * 32;  // warp M slab
    int wn = (wid & 1) * 32;   // warp N slab

    float acc[2][4][4];
#pragma unroll
    for (int i = 0; i < 2; i++)
#pragma unroll
        for (int j = 0; j < 4; j++)
#pragma unroll
            for (int q = 0; q < 4; q++) acc[i][j][q] = 0.f;

    // loader mapping
    int a_row  = tid >> 1;         // 0..127
    int a_half = tid & 1;          // k offset 0 / 8
    int b_row  = tid >> 2;         // 0..63
    int b_q    = tid & 3;          // k offset 0,4,8,12
    int a_grow = m0 + a_row;
    bool a_ok  = (a_grow < Nrows);
    const float* aptr = A + (size_t)a_grow * KDIM + a_half * 8;
    const float* bptr = W + (size_t)(j0 + b_row) * KDIM + b_q * 4;

    uint32_t a_st = a_row * SB32 + a_half * 4;
    uint32_t b_st = b_row * SB32 + b_q * 2;

    // prefetch chunk 0
    float4 av0, av1, bv;
    av0 = a_ok ? *(const float4*)(aptr)     : make_float4(0.f, 0.f, 0.f, 0.f);
    av1 = a_ok ? *(const float4*)(aptr + 4) : make_float4(0.f, 0.f, 0.f, 0.f);
    bv  = *(const float4*)(bptr);

    for (int it = 0; it < 16; it++) {
        int pp = it & 1;
        // ---- convert + store current chunk into ping-pong slot ----
        {
            float va[8] = {av0.x, av0.y, av0.z, av0.w, av1.x, av1.y, av1.z, av1.w};
            if (GNA) gn8_elu(va, gnA_w, gnA_b, it * 16 + a_half * 8);
            uint32_t wh[4], wl[4];
#pragma unroll
            for (int i = 0; i < 4; i++) {
                __nv_bfloat16 h0, l0, h1, l1;
                bf16_split(va[2 * i],     h0, l0);
                bf16_split(va[2 * i + 1], h1, l1);
                wh[i] = pack_bf16(h0, h1);
                wl[i] = pack_bf16(l0, l1);
            }
            *(uint4*)(As_hi[pp] + a_st) = make_uint4(wh[0], wh[1], wh[2], wh[3]);
            *(uint4*)(As_lo[pp] + a_st) = make_uint4(wl[0], wl[1], wl[2], wl[3]);

            float vb[4] = {bv.x, bv.y, bv.z, bv.w};
            __nv_bfloat16 h0, l0, h1, l1;
            bf16_split(vb[0], h0, l0); bf16_split(vb[1], h1, l1);
            uint32_t bh0 = pack_bf16(h0, h1), bl0 = pack_bf16(l0, l1);
            bf16_split(vb[2], h0, l0); bf16_split(vb[3], h1, l1);
            uint32_t bh1 = pack_bf16(h0, h1), bl1 = pack_bf16(l0, l1);
            *(uint2*)(Bs_hi[pp] + b_st) = make_uint2(bh0, bh1);
            *(uint2*)(Bs_lo[pp] + b_st) = make_uint2(bl0, bl1);
        }

        // ---- prefetch next chunk ----
        if (it < 15) {
            int k0 = (it + 1) * 16;
            av0 = a_ok ? *(const float4*)(aptr + k0)     : make_float4(0.f, 0.f, 0.f, 0.f);
            av1 = a_ok ? *(const float4*)(aptr + k0 + 4) : make_float4(0.f, 0.f, 0.f, 0.f);
            bv  = *(const float4*)(bptr + k0);
        }

        __syncthreads();   // single barrier per iter (ping-pong protects reuse)

        // ---- fragment loads + MMA ----
        uint32_t ah[2][4], al[2][4];
#pragma unroll
        for (int mt = 0; mt < 2; mt++) {
            int r0 = (wm + mt * 16 + grp) * SB32 + qid;
            int r1 = r0 + 8 * SB32;
            ah[mt][0] = As_hi[pp][r0];     ah[mt][1] = As_hi[pp][r1];
            ah[mt][2] = As_hi[pp][r0 + 4]; ah[mt][3] = As_hi[pp][r1 + 4];
            al[mt][0] = As_lo[pp][r0];     al[mt][1] = As_lo[pp][r1];
            al[mt][2] = As_lo[pp][r0 + 4]; al[mt][3] = As_lo[pp][r1 + 4];
        }
        uint32_t bh[4][2], bl[4][2];
#pragma unroll
        for (int nt = 0; nt < 4; nt++) {
            int rb = (wn + nt * 8 + grp) * SB32 + qid;
            bh[nt][0] = Bs_hi[pp][rb]; bh[nt][1] = Bs_hi[pp][rb + 4];
            bl[nt][0] = Bs_lo[pp][rb]; bl[nt][1] = Bs_lo[pp][rb + 4];
        }
#pragma unroll
        for (int mt = 0; mt < 2; mt++) {
#pragma unroll
            for (int nt = 0; nt < 4; nt++) {
                float* c = acc[mt][nt];
                mma_bf16(c[0], c[1], c[2], c[3],
                         ah[mt][0], ah[mt][1], ah[mt][2], ah[mt][3],
                         bh[nt][0], bh[nt][1]);
                mma_bf16(c[0], c[1], c[2], c[3],
                         ah[mt][0], ah[mt][1], ah[mt][2], ah[mt][3],
                         bl[nt][0], bl[nt][1]);
                mma_bf16(c[0], c[1], c[2], c[3],
                         al[mt][0], al[mt][1], al[mt][2], al[mt][3],
                         bh[nt][0], bh[nt][1]);
            }
        }
    }

    // ---- epilogue (optionally fused GroupNorm(8)+ELU) ----
#pragma unroll
    for (int mt = 0; mt < 2; mt++) {
        int row0 = m0 + wm + mt * 16 + grp;
        int row1 = row0 + 8;
#pragma unroll
        for (int nt = 0; nt < 4; nt++) {
            int col = j0 + wn + nt * 8 + qid * 2;
            float b0 = 0.f, b1 = 0.f;
            if (BIAS) { b0 = bias[col]; b1 = bias[col + 1]; }
            float v0 = acc[mt][nt][0] + b0;
            float v1 = acc[mt][nt][1] + b1;
            float v2 = acc[mt][nt][2] + b0;
            float v3 = acc[mt][nt][3] + b1;
            if (GNELU) {
                float s01 = v0 + v1, q01 = v0 * v0 + v1 * v1;
                float s23 = v2 + v3, q23 = v2 * v2 + v3 * v3;
                s01 += __shfl_xor_sync(0xffffffffu, s01, 1);
                q01 += __shfl_xor_sync(0xffffffffu, q01, 1);
                s23 += __shfl_xor_sync(0xffffffffu, s23, 1);
                q23 += __shfl_xor_sync(0xffffffffu, q23, 1);
                s01 += __shfl_xor_sync(0xffffffffu, s01, 2);
                q01 += __shfl_xor_sync(0xffffffffu, q01, 2);
                s23 += __shfl_xor_sync(0xffffffffu, s23, 2);
                q23 += __shfl_xor_sync(0xffffffffu, q23, 2);
                float mu0 = s01 * 0.125f;
                float iv0 = rsqrtf(q01 * 0.125f - mu0 * mu0 + 1e-5f);
                float mu1 = s23 * 0.125f;
                float iv1 = rsqrtf(q23 * 0.125f - mu1 * mu1 + 1e-5f);
                float w0 = gn_w[col], w1 = gn_w[col + 1];
                float gb0 = gn_b[col], gb1 = gn_b[col + 1];
                v0 = elu_f((v0 - mu0) * iv0 * w0 + gb0);
                v1 = elu_f((v1 - mu0) * iv0 * w1 + gb1);
                v2 = elu_f((v2 - mu1) * iv1 * w0 + gb0);
                v3 = elu_f((v3 - mu1) * iv1 * w1 + gb1);
            }
            if (row0 < Nrows) {
                float* p = C + (size_t)row0 * J + col;
                p[0] = v0; p[1] = v1;
            }
            if (row1 < Nrows) {
                float* p = C + (size_t)row1 * J + col;
                p[0] = v2; p[1] = v3;
            }
        }
    }
}

// =====================================================================
// Dual GEMM (lin2 + skip fused):  out[m][j] = bufB[m]·lin2_w[j]
//                                           + x[m]·skip_w[j] + biases
// =====================================================================
__global__ void __launch_bounds__(256)
dualgemm_kernel(const float* __restrict__ x,
                const float* __restrict__ w1,   // lin2_w [512,256]
                const float* __restrict__ w2,   // skip_w [512,256]
                const float* __restrict__ b1,
                const float* __restrict__ b2,
                float* __restrict__ C,
                int Nrows, int J)
{
    __shared__ uint32_t As_hi[2][128 * SB32];
    __shared__ uint32_t As_lo[2][128 * SB32];
    __shared__ uint32_t Bs_hi[2][64 * SB32];
    __shared__ uint32_t Bs_lo[2][64 * SB32];

    int tid  = threadIdx.x;
    int wid  = tid >> 5;
    int lane = tid & 31;
    int grp  = lane >> 2;
    int qid  = lane & 3;

    int m0 = blockIdx.y * 128;
    int j0 = blockIdx.x * 64;
    int wm = (wid >> 1) * 32;
    int wn = (wid & 1) * 32;

    float acc[2][4][4];
#pragma unroll
    for (int i = 0; i < 2; i++)
#pragma unroll
        for (int j = 0; j < 4; j++)
#pragma unroll
            for (int q = 0; q < 4; q++) acc[i][j][q] = 0.f;

    int a_row  = tid >> 1;
    int a_half = tid & 1;
    int b_row  = tid >> 2;
    int b_q    = tid & 3;
    int a_grow = m0 + a_row;
    bool a_ok  = (a_grow < Nrows);
    const float* aptr1 = g_bufB + (size_t)a_grow * KDIM + a_half * 8;
    const float* aptr2 = x      + (size_t)a_grow * KDIM + a_half * 8;
    const float* bptr1 = w1 + (size_t)(j0 + b_row) * KDIM + b_q * 4;
    const float* bptr2 = w2 + (size_t)(j0 + b_row) * KDIM + b_q * 4;

    uint32_t a_st = a_row * SB32 + a_half * 4;
    uint32_t b_st = b_row * SB32 + b_q * 2;

    float4 av0, av1, bv;
    av0 = a_ok ? *(const float4*)(aptr1)     : make_float4(0.f, 0.f, 0.f, 0.f);
    av1 = a_ok ? *(const float4*)(aptr1 + 4) : make_float4(0.f, 0.f, 0.f, 0.f);
    bv  = *(const float4*)(bptr1);

    for (int it = 0; it < 32; it++) {
        int pp = it & 1;
        {
            float va[8] = {av0.x, av0.y, av0.z, av0.w, av1.x, av1.y, av1.z, av1.w};
            uint32_t wh[4], wl[4];
#pragma unroll
            for (int i = 0; i < 4; i++) {
                __nv_bfloat16 h0, l0, h1, l1;
                bf16_split(va[2 * i],     h0, l0);
                bf16_split(va[2 * i + 1], h1, l1);
                wh[i] = pack_bf16(h0, h1);
                wl[i] = pack_bf16(l0, l1);
            }
            *(uint4*)(As_hi[pp] + a_st) = make_uint4(wh[0], wh[1], wh[2], wh[3]);
            *(uint4*)(As_lo[pp] + a_st) = make_uint4(wl[0], wl[1], wl[2], wl[3]);

            float vb[4] = {bv.x, bv.y, bv.z, bv.w};
            __nv_bfloat16 h0, l0, h1, l1;
            bf16_split(vb[0], h0, l0); bf16_split(vb[1], h1, l1);
            uint32_t bh0 = pack_bf16(h0, h1), bl0 = pack_bf16(l0, l1);
            bf16_split(vb[2], h0, l0); bf16_split(vb[3], h1, l1);
            uint32_t bh1 = pack_bf16(h0, h1), bl1 = pack_bf16(l0, l1);
            *(uint2*)(Bs_hi[pp] + b_st) = make_uint2(bh0, bh1);
            *(uint2*)(Bs_lo[pp] + b_st) = make_uint2(bl0, bl1);
        }

        if (it < 31) {
            int nit = it + 1;
            int k0 = (nit & 15) * 16;
            const float* ap = (nit < 16) ? aptr1 : aptr2;
            const float* bp = (nit < 16) ? bptr1 : bptr2;
            av0 = a_ok ? *(const float4*)(ap + k0)     : make_float4(0.f, 0.f, 0.f, 0.f);
            av1 = a_ok ? *(const float4*)(ap + k0 + 4) : make_float4(0.f, 0.f, 0.f, 0.f);
            bv  = *(const float4*)(bp + k0);
        }

        __syncthreads();

        uint32_t ah[2][4], al[2][4];
#pragma unroll
        for (int mt = 0; mt < 2; mt++) {
            int r0 = (wm + mt * 16 + grp) * SB32 + qid;
            int r1 = r0 + 8 * SB32;
            ah[mt][0] = As_hi[pp][r0];     ah[mt][1] = As_hi[pp][r1];
            ah[mt][2] = As_hi[pp][r0 + 4]; ah[mt][3] = As_hi[pp][r1 + 4];
            al[mt][0] = As_lo[pp][r0];     al[mt][1] = As_lo[pp][r1];
            al[mt][2] = As_lo[pp][r0 + 4]; al[mt][3] = As_lo[pp][r1 + 4];
        }
        uint32_t bh[4][2], bl[4][2];
#pragma unroll
        for (int nt = 0; nt < 4; nt++) {
            int rb = (wn + nt * 8 + grp) * SB32 + qid;
            bh[nt][0] = Bs_hi[pp][rb]; bh[nt][1] = Bs_hi[pp][rb + 4];
            bl[nt][0] = Bs_lo[pp][rb]; bl[nt][1] = Bs_lo[pp][rb + 4];
        }
#pragma unroll
        for (int mt = 0; mt < 2; mt++) {
#pragma unroll
            for (int nt = 0; nt < 4; nt++) {
                float* c = acc[mt][nt];
                mma_bf16(c[0], c[1], c[2], c[3],
                         ah[mt][0], ah[mt][1], ah[mt][2], ah[mt][3],
                         bh[nt][0], bh[nt][1]);
                mma_bf16(c[0], c[1], c[2], c[3],
                         ah[mt][0], ah[mt][1], ah[mt][2], ah[mt][3],
                         bl[nt][0], bl[nt][1]);
                mma_bf16(c[0], c[1], c[2], c[3],
                         al[mt][0], al[mt][1], al[mt][2], al[mt][3],
                         bh[nt][0], bh[nt][1]);
            }
        }
    }

#pragma unroll
    for (int mt = 0; mt < 2; mt++) {
        int row0 = m0 + wm + mt * 16 + grp;
        int row1 = row0 + 8;
#pragma unroll
        for (int nt = 0; nt < 4; nt++) {
            int col = j0 + wn + nt * 8 + qid * 2;
            float b0 = b1[col] + b2[col];
            float bb1 = b1[col + 1] + b2[col + 1];
            if (row0 < Nrows) {
                float* p = C + (size_t)row0 * J + col;
                p[0] = acc[mt][nt][0] + b0;
                p[1] = acc[mt][nt][1] + bb1;
            }
            if (row1 < Nrows) {
                float* p = C + (size_t)row1 * J + col;
                p[0] = acc[mt][nt][2] + b0;
                p[1] = acc[mt][nt][3] + bb1;
            }
        }
    }
}

// Read edge endpoint idx (0..2E-1 flattened) honoring detected dtype.
__device__ __forceinline__ int edge_at(const void* ei, long long flat)
{
    if (g_is64) return (int)((const long long*)ei)[flat];
    return ((const int*)ei)[flat];
}

__global__ void detect_dtype_kernel(const void* ei, int n)
{
    if (threadIdx.x == 0 && blockIdx.x == 0) {
        const long long* p = (const long long*)ei;
        int ok = 1;
        for (int i = 0; i < 64; i++) {
            long long v = p[i];
            if (v < 0 || v >= n) { ok = 0; break; }
        }
        g_is64 = ok;
    }
}

// =====================================================================
// Per-node attention projections on h = g_bufH.  One warp per node.
// =====================================================================
__global__ void node_dots_kernel(const float* __restrict__ a_src,
                                 const float* __restrict__ a_dst, int n)
{
    int warp = (blockIdx.x * blockDim.x + threadIdx.x) >> 5;
    int lane = threadIdx.x & 31;
    if (warp >= n) return;
    const float* row = g_bufH + (size_t)warp * 256;
    float s1 = 0.f, s2 = 0.f;
#pragma unroll
    for (int i = 0; i < 8; i++) {
        int c = lane + i * 32;
        float v = row[c];
        s1 += v * a_src[c];
        s2 += v * a_dst[c];
    }
#pragma unroll
    for (int o = 16; o; o >>= 1) {
        s1 += __shfl_down_sync(0xffffffff, s1, o);
        s2 += __shfl_down_sync(0xffffffff, s2, o);
    }
    if (lane == 0) { g_asrc[warp] = s1; g_adst[warp] = s2; }
}

// ------------------------- CSR build kernels --------------------------------
__global__ void zero_deg_kernel(int n)
{
    int i = blockIdx.x * blockDim.x + threadIdx.x;
    if (i < n) g_deg[i] = 0;
}

__global__ void hist_kernel(const void* __restrict__ ei, int E, int n)
{
    int t = blockIdx.x * blockDim.x + threadIdx.x;
    if (t >= E + n) return;
    int d = (t < E) ? edge_at(ei, (long long)E + t) : (t - E);
    if ((unsigned)d >= (unsigned)n) return;
    atomicAdd(&g_deg[d], 1);
}

// ---- parallel 3-phase scan ----
__global__ void scan1_kernel(int n)
{
    __shared__ int wsum[32];
    int tid = threadIdx.x;
    int i = blockIdx.x * 1024 + tid;
    int v = (i < n) ? g_deg[i] : 0;
    int s = v;
#pragma unroll
    for (int o = 16; o; o >>= 1) s += __shfl_down_sync(0xffffffff, s, o);
    if ((tid & 31) == 0) wsum[tid >> 5] = s;
    __syncthreads();
    if (tid < 32) {
        int t = wsum[tid];
#pragma unroll
        for (int o = 16; o; o >>= 1) t += __shfl_down_sync(0xffffffff, t, o);
        if (tid == 0) g_blksum[blockIdx.x] = t;
    }
}
__global__ void scan2_kernel(int nb)
{
    int tid = threadIdx.x;  // 64 threads
    int v = (tid < nb) ? g_blksum[tid] : 0;
    int x = v;
    __shared__ int sh[64];
    sh[tid] = v;
    __syncthreads();
    for (int o = 1; o < 64; o <<= 1) {
        int t = (tid >= o) ? sh[tid - o] : 0;
        __syncthreads();
        sh[tid] += t;
        __syncthreads();
    }
    if (tid < nb) g_blkoff[tid] = sh[tid] - x;  // exclusive
}
__global__ void scan3_kernel(int n)
{
    __shared__ int wsum[32];
    int tid = threadIdx.x;
    int lane = tid & 31, wid = tid >> 5;
    int i = blockIdx.x * 1024 + tid;
    int v = (i < n) ? g_deg[i] : 0;
    int x = v;
#pragma unroll
    for (int o = 1; o < 32; o <<= 1) {
        int t = __shfl_up_sync(0xffffffff, x, o);
        if (lane >= o) x += t;
    }
    if (lane == 31) wsum[wid] = x;
    __syncthreads();
    if (wid == 0) {
        int w = wsum[lane];
#pragma unroll
        for (int o = 1; o < 32; o <<= 1) {
            int t = __shfl_up_sync(0xffffffff, w, o);
            if (lane >= o) w += t;
        }
        wsum[lane] = w;
    }
    __syncthreads();
    int excl = x - v + (wid ? wsum[wid - 1] : 0) + g_blkoff[blockIdx.x];
    if (i < n) {
        g_off[i] = excl;
        g_cursor[i] = excl;
        if (i == n - 1) g_off[n] = excl + v;
    }
}

__global__ void scatter_kernel(const void* __restrict__ ei, int E, int n)
{
    int t = blockIdx.x * blockDim.x + threadIdx.x;
    if (t >= E + n) return;
    int s, d;
    if (t < E) {
        s = edge_at(ei, t);
        d = edge_at(ei, (long long)E + t);
    } else {
        s = t - E; d = t - E;
    }
    if ((unsigned)d >= (unsigned)n || (unsigned)s >= (unsigned)n) return;
    int p = atomicAdd(&g_cursor[d], 1);
    g_srcs[p] = s;
}

// =====================================================================
// GAT aggregation + fused GroupNorm(8)+ELU.  One WARP per node; lane l
// owns channels [8l, 8l+8) = exactly one GN group (all in-register).
// Softmax without max-subtraction (alpha ratio is identical; |e| is
// small here so exp cannot overflow).  Two passes over the edge list.
// =====================================================================
__global__ void gat_agg_kernel(const float* __restrict__ bias,
                               const float* __restrict__ gn_w,
                               const float* __restrict__ gn_b,
                               int out_id, int n)
{
    float* out = resolve_buf(out_id, nullptr);
    int warp = (blockIdx.x * blockDim.x + threadIdx.x) >> 5;
    int lane = threadIdx.x & 31;
    if (warp >= n) return;
    int s0 = g_off[warp], s1 = g_off[warp + 1];
    float ad = g_adst[warp];

    // pass 1: s = sum over edges of exp(leaky_relu(asrc+adst))
    float s = 0.f;
    for (int j = s0 + lane; j < s1; j += 32) {
        float e = g_asrc[g_srcs[j]] + ad;
        e = (e > 0.f) ? e : 0.2f * e;
        s += expf(e);
    }
#pragma unroll
    for (int o = 16; o; o >>= 1) s += __shfl_xor_sync(0xffffffffu, s, o);
    float rinv = 1.0f / (s + 1e-16f);

    // pass 2: weighted accumulate; each lane holds 8 channels
    float acc[8] = {0.f, 0.f, 0.f, 0.f, 0.f, 0.f, 0.f, 0.f};
    for (int base = s0; base < s1; base += 32) {
        int j = base + lane;
        int sn = 0; float al = 0.f;
        if (j < s1) {
            sn = g_srcs[j];
            float e = g_asrc[sn] + ad;
            e = (e > 0.f) ? e : 0.2f * e;
            al = expf(e) * rinv;
        }
        int cnt = min(32, s1 - base);
        for (int k = 0; k < cnt; k++) {
            int   src = __shfl_sync(0xffffffffu, sn, k);
            float a   = __shfl_sync(0xffffffffu, al, k);
            const float4* hp = (const float4*)(g_bufH + (size_t)src * 256 + lane * 8);
            float4 h0 = hp[0];
            float4 h1 = hp[1];
            acc[0] += a * h0.x; acc[1] += a * h0.y;
            acc[2] += a * h0.z; acc[3] += a * h0.w;
            acc[4] += a * h1.x; acc[5] += a * h1.y;
            acc[6] += a * h1.z; acc[7] += a * h1.w;
        }
    }

    // fused GroupNorm(8)+ELU — lane's 8 channels = one full group
    int c0 = lane * 8;
    float v[8];
#pragma unroll
    for (int i = 0; i < 8; i++) v[i] = acc[i] + bias[c0 + i];
    gn8_elu(v, gn_w, gn_b, c0);
    float* orow = out + (size_t)warp * 256 + c0;
    *(float4*)(orow)     = make_float4(v[0], v[1], v[2], v[3]);
    *(float4*)(orow + 4) = make_float4(v[4], v[5], v[6], v[7]);
}

// ============================== launcher =====================================
extern "C" void kernel_launch(void* const* d_in, const int* in_sizes, int n_in,
                              void* d_out, int out_size)
{
    const float* x      = (const float*)d_in[0];
    const void*  ei     = d_in[1];
    const float* pre_w  = (const float*)d_in[2];
    const float* pre_b  = (const float*)d_in[3];
    const float* lin1_w = (const float*)d_in[4];
    const float* lin1_b = (const float*)d_in[5];
    const float* n1_w   = (const float*)d_in[6];
    const float* n1_b   = (const float*)d_in[7];
    const float* g1_w   = (const float*)d_in[8];
    const float* g1_as  = (const float*)d_in[9];
    const float* g1_ad  = (const float*)d_in[10];
    const float* g1_b   = (const float*)d_in[11];
    const float* n2_w   = (const float*)d_in[12];
    const float* n2_b   = (const float*)d_in[13];
    const float* g2_w   = (const float*)d_in[14];
    const float* g2_as  = (const float*)d_in[15];
    const float* g2_ad  = (const float*)d_in[16];
    const float* g2_b   = (const float*)d_in[17];
    const float* n3_w   = (const float*)d_in[18];
    const float* n3_b   = (const float*)d_in[19];
    const float* lin2_w = (const float*)d_in[20];
    const float* lin2_b = (const float*)d_in[21];
    const float* skip_w = (const float*)d_in[22];
    const float* skip_b = (const float*)d_in[23];
    float* out = (float*)d_out;

    int N = in_sizes[0] / CIN;
    int E = in_sizes[1] / 2;
    int ET = E + N;

    int warpBlocks = (N * 32 + 255) / 256;
    int eBlocks    = (ET + 255) / 256;
    int nBlocks    = (N + 255) / 256;
    int mBlocks    = (N + 127) / 128;
    int sBlocks    = (N + 1023) / 1024;

    // ---- CSR build start ----
    detect_dtype_kernel<<<1, 32>>>(ei, N);
    zero_deg_kernel<<<nBlocks, 256>>>(N);
    hist_kernel<<<eBlocks, 256>>>(ei, E, N);
    scan1_kernel<<<sBlocks, 1024>>>(N);
    scan2_kernel<<<1, 64>>>(sBlocks);

    // ---- lin1: x --(fused pre_norm GN+ELU on A)--> GEMM --(fused GN1+ELU)--> bufB
    bfgemm_kernel<true, true, true><<<dim3(HDIM / 64, mBlocks), 256>>>(
        BUF_EXT, x, lin1_w, lin1_b, pre_w, pre_b, n1_w, n1_b,
        BUF_B, nullptr, N, HDIM);

    scan3_kernel<<<sBlocks, 1024>>>(N);
    scatter_kernel<<<eBlocks, 256>>>(ei, E, N);

    // ---- GAT layer 1 : bufB -> (h=bufH) -> bufA (agg + fused GN2+ELU) ----
    bfgemm_kernel<false, false, false><<<dim3(HDIM / 64, mBlocks), 256>>>(
        BUF_B, nullptr, g1_w, nullptr, nullptr, nullptr, nullptr, nullptr,
        BUF_H, nullptr, N, HDIM);
    node_dots_kernel<<<warpBlocks, 256>>>(g1_as, g1_ad, N);
    gat_agg_kernel<<<warpBlocks, 256>>>(g1_b, n2_w, n2_b, BUF_A, N);

    // ---- GAT layer 2 : bufA -> (h=bufH) -> bufB (agg + fused GN3+ELU) ----
    bfgemm_kernel<false, false, false><<<dim3(HDIM / 64, mBlocks), 256>>>(
        BUF_A, nullptr, g2_w, nullptr, nullptr, nullptr, nullptr, nullptr,
        BUF_H, nullptr, N, HDIM);
    node_dots_kernel<<<warpBlocks, 256>>>(g2_as, g2_ad, N);
    gat_agg_kernel<<<warpBlocks, 256>>>(g2_b, n3_w, n3_b, BUF_B, N);

    // ---- fused lin2 + skip -> out (single pass, no ACC read) ----
    dualgemm_kernel<<<dim3(COUT / 64, mBlocks), 256>>>(
        x, lin2_w, skip_w, lin2_b, skip_b, out, N, COUT);
}

// round 17
// speedup vs baseline: 1.7079x; 1.1245x over previous
#include <cuda_runtime.h>
#include <cuda_fp16.h>
#include <math.h>
#include <stdint.h>

// ---------------- Problem-size constants (fixed by the dataset) -------------
#define NMAX   40000
#define EMAX   640000
#define ETMAX  (EMAX + NMAX)      // edges + self loops
#define CIN    256
#define HDIM   256
#define COUT   512
#define KDIM   256                // every single GEMM in this model has K = 256

// ---------------- Static device scratch (no allocation allowed) -------------
__device__ float g_bufA[(size_t)NMAX * HDIM];
__device__ float g_bufB[(size_t)NMAX * HDIM];
__device__ float g_bufH[(size_t)NMAX * HDIM];
__device__ float g_asrc[NMAX];
__device__ float g_adst[NMAX];
__device__ int   g_deg[NMAX];
__device__ int   g_off[NMAX + 1];
__device__ int   g_cursor[NMAX];
__device__ int   g_srcs[ETMAX];
__device__ int   g_is64;          // 1 if edge_index is int64, 0 if int32
__device__ int   g_blksum[64];
__device__ int   g_blkoff[64];

// Buffer-id resolution (device side).
#define BUF_A 0
#define BUF_B 1
#define BUF_H 2
#define BUF_EXT (-1)

__device__ __forceinline__ float* resolve_buf(int id, float* ext)
{
    switch (id) {
        case BUF_A: return g_bufA;
        case BUF_B: return g_bufB;
        case BUF_H: return g_bufH;
        default:    return ext;
    }
}
__device__ __forceinline__ const float* resolve_cbuf(int id, const float* ext)
{
    switch (id) {
        case BUF_A: return g_bufA;
        case BUF_B: return g_bufB;
        case BUF_H: return g_bufH;
        default:    return ext;
    }
}

// ---------------- fp16 helpers ----------------------------------------------
// split a = hi + lo (both fp16). |lo| <= ~2^-12 |a|; dropping a*lo_b in the
// 2-pass MMA leaves per-product error ~2^-12 |a||b| (calibrated ~2e-4 e2e).
__device__ __forceinline__ void f16_split(float a, __half& hi, __half& lo)
{
    hi = __float2half_rn(a);
    lo = __float2half_rn(a - __half2float(hi));
}
__device__ __forceinline__ uint32_t pack_f16(__half a, __half b)
{
    return (uint32_t)__half_as_ushort(a) | ((uint32_t)__half_as_ushort(b) << 16);
}

__device__ __forceinline__ void mma_f16(float& c0, float& c1, float& c2, float& c3,
                                        uint32_t a0, uint32_t a1, uint32_t a2, uint32_t a3,
                                        uint32_t b0, uint32_t b1)
{
    asm volatile(
        "mma.sync.aligned.m16n8k16.row.col.f32.f16.f16.f32 "
        "{%0,%1,%2,%3}, {%4,%5,%6,%7}, {%8,%9}, {%0,%1,%2,%3};"
        : "+f"(c0), "+f"(c1), "+f"(c2), "+f"(c3)
        : "r"(a0), "r"(a1), "r"(a2), "r"(a3), "r"(b0), "r"(b1));
}

__device__ __forceinline__ float elu_f(float y)
{
    return (y > 0.f) ? y : expm1f(y);
}

// apply GroupNorm(8)+ELU to 8 consecutive floats held in registers
__device__ __forceinline__ void gn8_elu(float* v, const float* w, const float* b, int c0)
{
    float mu = 0.f;
#pragma unroll
    for (int i = 0; i < 8; i++) mu += v[i];
    mu *= 0.125f;
    float var = 0.f;
#pragma unroll
    for (int i = 0; i < 8; i++) { float d = v[i] - mu; var += d * d; }
    var *= 0.125f;
    float iv = rsqrtf(var + 1e-5f);
    float4 w0 = *(const float4*)(w + c0);
    float4 w1 = *(const float4*)(w + c0 + 4);
    float4 b0 = *(const float4*)(b + c0);
    float4 b1 = *(const float4*)(b + c0 + 4);
    float ww[8] = {w0.x, w0.y, w0.z, w0.w, w1.x, w1.y, w1.z, w1.w};
    float bb[8] = {b0.x, b0.y, b0.z, b0.w, b1.x, b1.y, b1.z, b1.w};
#pragma unroll
    for (int i = 0; i < 8; i++)
        v[i] = elu_f((v[i] - mu) * iv * ww[i] + bb[i]);
}

// =====================================================================
// 2-pass split-fp16 tensor-core GEMM:  C[m][j] = sum_k A[m][k]*W[j][k]
// A split hi+lo (fp16), B rounded to fp16:  D = hi_a*b + lo_a*b.
// Tile BM=128, BN=64, BK=16; 256 threads = 8 warps in 4(M) x 2(N);
// each warp computes 32x32 via 2x4 m16n8k16 fragments.
// Register prefetch + smem ping-pong => one __syncthreads per K-iter.
// GNA: fuse GroupNorm(8)+ELU onto the A operand.
// GNELU: fused GroupNorm(8)+ELU epilogue on the output.
// =====================================================================
#define SB32 12    // row stride in u32 (24 halfs = 48B; (12r+q) mod 32 conflict-free)

template <bool BIAS, bool GNA, bool GNELU>
__global__ void __launch_bounds__(256)
bfgemm_kernel(int A_id, const float* __restrict__ A_ext,
              const float* __restrict__ W,
              const float* __restrict__ bias,
              const float* __restrict__ gnA_w,
              const float* __restrict__ gnA_b,
              const float* __restrict__ gn_w,
              const float* __restrict__ gn_b,
              int C_id, float* __restrict__ C_ext,
              int Nrows, int J)
{
    const float* A = resolve_cbuf(A_id, A_ext);
    float* C = resolve_buf(C_id, C_ext);

    __shared__ uint32_t As_hi[2][128 * SB32];
    __shared__ uint32_t As_lo[2][128 * SB32];
    __shared__ uint32_t Bs[2][64 * SB32];

    int tid  = threadIdx.x;
    int wid  = tid >> 5;
    int lane = tid & 31;
    int grp  = lane >> 2;      // 0..7
    int qid  = lane & 3;       // 0..3

    int m0 = blockIdx.y * 128;
    int j0 = blockIdx.x * 64;

    int wm = (wid >> 1) * 32;  // warp M slab
    int wn = (wid & 1) * 32;   // warp N slab

    float acc[2][4][4];
#pragma unroll
    for (int i = 0; i < 2; i++)
#pragma unroll
        for (int j = 0; j < 4; j++)
#pragma unroll
            for (int q = 0; q < 4; q++) acc[i][j][q] = 0.f;

    // loader mapping
    int a_row  = tid >> 1;         // 0..127
    int a_half = tid & 1;          // k offset 0 / 8
    int b_row  = tid >> 2;         // 0..63
    int b_q    = tid & 3;          // k offset 0,4,8,12
    int a_grow = m0 + a_row;
    bool a_ok  = (a_grow < Nrows);
    const float* aptr = A + (size_t)a_grow * KDIM + a_half * 8;
    const float* bptr = W + (size_t)(j0 + b_row) * KDIM + b_q * 4;

    uint32_t a_st = a_row * SB32 + a_half * 4;
    uint32_t b_st = b_row * SB32 + b_q * 2;

    // prefetch chunk 0
    float4 av0, av1, bv;
    av0 = a_ok ? *(const float4*)(aptr)     : make_float4(0.f, 0.f, 0.f, 0.f);
    av1 = a_ok ? *(const float4*)(aptr + 4) : make_float4(0.f, 0.f, 0.f, 0.f);
    bv  = *(const float4*)(bptr);

    for (int it = 0; it < 16; it++) {
        int pp = it & 1;
        // ---- convert + store current chunk into ping-pong slot ----
        {
            float va[8] = {av0.x, av0.y, av0.z, av0.w, av1.x, av1.y, av1.z, av1.w};
            if (GNA) gn8_elu(va, gnA_w, gnA_b, it * 16 + a_half * 8);
            uint32_t wh[4], wl[4];
#pragma unroll
            for (int i = 0; i < 4; i++) {
                __half h0, l0, h1, l1;
                f16_split(va[2 * i],     h0, l0);
                f16_split(va[2 * i + 1], h1, l1);
                wh[i] = pack_f16(h0, h1);
                wl[i] = pack_f16(l0, l1);
            }
            *(uint4*)(As_hi[pp] + a_st) = make_uint4(wh[0], wh[1], wh[2], wh[3]);
            *(uint4*)(As_lo[pp] + a_st) = make_uint4(wl[0], wl[1], wl[2], wl[3]);

            // B: single fp16 (rounded)
            uint32_t b0 = pack_f16(__float2half_rn(bv.x), __float2half_rn(bv.y));
            uint32_t b1 = pack_f16(__float2half_rn(bv.z), __float2half_rn(bv.w));
            *(uint2*)(Bs[pp] + b_st) = make_uint2(b0, b1);
        }

        // ---- prefetch next chunk ----
        if (it < 15) {
            int k0 = (it + 1) * 16;
            av0 = a_ok ? *(const float4*)(aptr + k0)     : make_float4(0.f, 0.f, 0.f, 0.f);
            av1 = a_ok ? *(const float4*)(aptr + k0 + 4) : make_float4(0.f, 0.f, 0.f, 0.f);
            bv  = *(const float4*)(bptr + k0);
        }

        __syncthreads();   // single barrier per iter (ping-pong protects reuse)

        // ---- fragment loads + MMA (2 passes: hi_a*b, lo_a*b) ----
        uint32_t ah[2][4], al[2][4];
#pragma unroll
        for (int mt = 0; mt < 2; mt++) {
            int r0 = (wm + mt * 16 + grp) * SB32 + qid;
            int r1 = r0 + 8 * SB32;
            ah[mt][0] = As_hi[pp][r0];     ah[mt][1] = As_hi[pp][r1];
            ah[mt][2] = As_hi[pp][r0 + 4]; ah[mt][3] = As_hi[pp][r1 + 4];
            al[mt][0] = As_lo[pp][r0];     al[mt][1] = As_lo[pp][r1];
            al[mt][2] = As_lo[pp][r0 + 4]; al[mt][3] = As_lo[pp][r1 + 4];
        }
        uint32_t bh[4][2];
#pragma unroll
        for (int nt = 0; nt < 4; nt++) {
            int rb = (wn + nt * 8 + grp) * SB32 + qid;
            bh[nt][0] = Bs[pp][rb]; bh[nt][1] = Bs[pp][rb + 4];
        }
#pragma unroll
        for (int mt = 0; mt < 2; mt++) {
#pragma unroll
            for (int nt = 0; nt < 4; nt++) {
                float* c = acc[mt][nt];
                mma_f16(c[0], c[1], c[2], c[3],
                        ah[mt][0], ah[mt][1], ah[mt][2], ah[mt][3],
                        bh[nt][0], bh[nt][1]);
                mma_f16(c[0], c[1], c[2], c[3],
                        al[mt][0], al[mt][1], al[mt][2], al[mt][3],
                        bh[nt][0], bh[nt][1]);
            }
        }
    }

    // ---- epilogue (optionally fused GroupNorm(8)+ELU) ----
#pragma unroll
    for (int mt = 0; mt < 2; mt++) {
        int row0 = m0 + wm + mt * 16 + grp;
        int row1 = row0 + 8;
#pragma unroll
        for (int nt = 0; nt < 4; nt++) {
            int col = j0 + wn + nt * 8 + qid * 2;
            float b0 = 0.f, b1 = 0.f;
            if (BIAS) { b0 = bias[col]; b1 = bias[col + 1]; }
            float v0 = acc[mt][nt][0] + b0;
            float v1 = acc[mt][nt][1] + b1;
            float v2 = acc[mt][nt][2] + b0;
            float v3 = acc[mt][nt][3] + b1;
            if (GNELU) {
                float s01 = v0 + v1, q01 = v0 * v0 + v1 * v1;
                float s23 = v2 + v3, q23 = v2 * v2 + v3 * v3;
                s01 += __shfl_xor_sync(0xffffffffu, s01, 1);
                q01 += __shfl_xor_sync(0xffffffffu, q01, 1);
                s23 += __shfl_xor_sync(0xffffffffu, s23, 1);
                q23 += __shfl_xor_sync(0xffffffffu, q23, 1);
                s01 += __shfl_xor_sync(0xffffffffu, s01, 2);
                q01 += __shfl_xor_sync(0xffffffffu, q01, 2);
                s23 += __shfl_xor_sync(0xffffffffu, s23, 2);
                q23 += __shfl_xor_sync(0xffffffffu, q23, 2);
                float mu0 = s01 * 0.125f;
                float iv0 = rsqrtf(q01 * 0.125f - mu0 * mu0 + 1e-5f);
                float mu1 = s23 * 0.125f;
                float iv1 = rsqrtf(q23 * 0.125f - mu1 * mu1 + 1e-5f);
                float w0 = gn_w[col], w1 = gn_w[col + 1];
                float gb0 = gn_b[col], gb1 = gn_b[col + 1];
                v0 = elu_f((v0 - mu0) * iv0 * w0 + gb0);
                v1 = elu_f((v1 - mu0) * iv0 * w1 + gb1);
                v2 = elu_f((v2 - mu1) * iv1 * w0 + gb0);
                v3 = elu_f((v3 - mu1) * iv1 * w1 + gb1);
            }
            if (row0 < Nrows) {
                float* p = C + (size_t)row0 * J + col;
                p[0] = v0; p[1] = v1;
            }
            if (row1 < Nrows) {
                float* p = C + (size_t)row1 * J + col;
                p[0] = v2; p[1] = v3;
            }
        }
    }
}

// =====================================================================
// Dual GEMM (lin2 + skip fused):  out[m][j] = bufB[m]·lin2_w[j]
//                                           + x[m]·skip_w[j] + biases
// Same 2-pass fp16 scheme; K total 512 (32 iters).
// =====================================================================
__global__ void __launch_bounds__(256)
dualgemm_kernel(const float* __restrict__ x,
                const float* __restrict__ w1,   // lin2_w [512,256]
                const float* __restrict__ w2,   // skip_w [512,256]
                const float* __restrict__ b1,
                const float* __restrict__ b2,
                float* __restrict__ C,
                int Nrows, int J)
{
    __shared__ uint32_t As_hi[2][128 * SB32];
    __shared__ uint32_t As_lo[2][128 * SB32];
    __shared__ uint32_t Bs[2][64 * SB32];

    int tid  = threadIdx.x;
    int wid  = tid >> 5;
    int lane = tid & 31;
    int grp  = lane >> 2;
    int qid  = lane & 3;

    int m0 = blockIdx.y * 128;
    int j0 = blockIdx.x * 64;
    int wm = (wid >> 1) * 32;
    int wn = (wid & 1) * 32;

    float acc[2][4][4];
#pragma unroll
    for (int i = 0; i < 2; i++)
#pragma unroll
        for (int j = 0; j < 4; j++)
#pragma unroll
            for (int q = 0; q < 4; q++) acc[i][j][q] = 0.f;

    int a_row  = tid >> 1;
    int a_half = tid & 1;
    int b_row  = tid >> 2;
    int b_q    = tid & 3;
    int a_grow = m0 + a_row;
    bool a_ok  = (a_grow < Nrows);
    const float* aptr1 = g_bufB + (size_t)a_grow * KDIM + a_half * 8;
    const float* aptr2 = x      + (size_t)a_grow * KDIM + a_half * 8;
    const float* bptr1 = w1 + (size_t)(j0 + b_row) * KDIM + b_q * 4;
    const float* bptr2 = w2 + (size_t)(j0 + b_row) * KDIM + b_q * 4;

    uint32_t a_st = a_row * SB32 + a_half * 4;
    uint32_t b_st = b_row * SB32 + b_q * 2;

    float4 av0, av1, bv;
    av0 = a_ok ? *(const float4*)(aptr1)     : make_float4(0.f, 0.f, 0.f, 0.f);
    av1 = a_ok ? *(const float4*)(aptr1 + 4) : make_float4(0.f, 0.f, 0.f, 0.f);
    bv  = *(const float4*)(bptr1);

    for (int it = 0; it < 32; it++) {
        int pp = it & 1;
        {
            float va[8] = {av0.x, av0.y, av0.z, av0.w, av1.x, av1.y, av1.z, av1.w};
            uint32_t wh[4], wl[4];
#pragma unroll
            for (int i = 0; i < 4; i++) {
                __half h0, l0, h1, l1;
                f16_split(va[2 * i],     h0, l0);
                f16_split(va[2 * i + 1], h1, l1);
                wh[i] = pack_f16(h0, h1);
                wl[i] = pack_f16(l0, l1);
            }
            *(uint4*)(As_hi[pp] + a_st) = make_uint4(wh[0], wh[1], wh[2], wh[3]);
            *(uint4*)(As_lo[pp] + a_st) = make_uint4(wl[0], wl[1], wl[2], wl[3]);

            uint32_t b0 = pack_f16(__float2half_rn(bv.x), __float2half_rn(bv.y));
            uint32_t b1v = pack_f16(__float2half_rn(bv.z), __float2half_rn(bv.w));
            *(uint2*)(Bs[pp] + b_st) = make_uint2(b0, b1v);
        }

        if (it < 31) {
            int nit = it + 1;
            int k0 = (nit & 15) * 16;
            const float* ap = (nit < 16) ? aptr1 : aptr2;
            const float* bp = (nit < 16) ? bptr1 : bptr2;
            av0 = a_ok ? *(const float4*)(ap + k0)     : make_float4(0.f, 0.f, 0.f, 0.f);
            av1 = a_ok ? *(const float4*)(ap + k0 + 4) : make_float4(0.f, 0.f, 0.f, 0.f);
            bv  = *(const float4*)(bp + k0);
        }

        __syncthreads();

        uint32_t ah[2][4], al[2][4];
#pragma unroll
        for (int mt = 0; mt < 2; mt++) {
            int r0 = (wm + mt * 16 + grp) * SB32 + qid;
            int r1 = r0 + 8 * SB32;
            ah[mt][0] = As_hi[pp][r0];     ah[mt][1] = As_hi[pp][r1];
            ah[mt][2] = As_hi[pp][r0 + 4]; ah[mt][3] = As_hi[pp][r1 + 4];
            al[mt][0] = As_lo[pp][r0];     al[mt][1] = As_lo[pp][r1];
            al[mt][2] = As_lo[pp][r0 + 4]; al[mt][3] = As_lo[pp][r1 + 4];
        }
        uint32_t bh[4][2];
#pragma unroll
        for (int nt = 0; nt < 4; nt++) {
            int rb = (wn + nt * 8 + grp) * SB32 + qid;
            bh[nt][0] = Bs[pp][rb]; bh[nt][1] = Bs[pp][rb + 4];
        }
#pragma unroll
        for (int mt = 0; mt < 2; mt++) {
#pragma unroll
            for (int nt = 0; nt < 4; nt++) {
                float* c = acc[mt][nt];
                mma_f16(c[0], c[1], c[2], c[3],
                        ah[mt][0], ah[mt][1], ah[mt][2], ah[mt][3],
                        bh[nt][0], bh[nt][1]);
                mma_f16(c[0], c[1], c[2], c[3],
                        al[mt][0], al[mt][1], al[mt][2], al[mt][3],
                        bh[nt][0], bh[nt][1]);
            }
        }
    }

#pragma unroll
    for (int mt = 0; mt < 2; mt++) {
        int row0 = m0 + wm + mt * 16 + grp;
        int row1 = row0 + 8;
#pragma unroll
        for (int nt = 0; nt < 4; nt++) {
            int col = j0 + wn + nt * 8 + qid * 2;
            float b0 = b1[col] + b2[col];
            float bb1 = b1[col + 1] + b2[col + 1];
            if (row0 < Nrows) {
                float* p = C + (size_t)row0 * J + col;
                p[0] = acc[mt][nt][0] + b0;
                p[1] = acc[mt][nt][1] + bb1;
            }
            if (row1 < Nrows) {
                float* p = C + (size_t)row1 * J + col;
                p[0] = acc[mt][nt][2] + b0;
                p[1] = acc[mt][nt][3] + bb1;
            }
        }
    }
}

// Read edge endpoint idx (0..2E-1 flattened) honoring detected dtype.
__device__ __forceinline__ int edge_at(const void* ei, long long flat)
{
    if (g_is64) return (int)((const long long*)ei)[flat];
    return ((const int*)ei)[flat];
}

__global__ void detect_dtype_kernel(const void* ei, int n)
{
    if (threadIdx.x == 0 && blockIdx.x == 0) {
        const long long* p = (const long long*)ei;
        int ok = 1;
        for (int i = 0; i < 64; i++) {
            long long v = p[i];
            if (v < 0 || v >= n) { ok = 0; break; }
        }
        g_is64 = ok;
    }
}

// =====================================================================
// Per-node attention projections on h = g_bufH.  One warp per node.
// =====================================================================
__global__ void node_dots_kernel(const float* __restrict__ a_src,
                                 const float* __restrict__ a_dst, int n)
{
    int warp = (blockIdx.x * blockDim.x + threadIdx.x) >> 5;
    int lane = threadIdx.x & 31;
    if (warp >= n) return;
    const float* row = g_bufH + (size_t)warp * 256;
    float s1 = 0.f, s2 = 0.f;
#pragma unroll
    for (int i = 0; i < 8; i++) {
        int c = lane + i * 32;
        float v = row[c];
        s1 += v * a_src[c];
        s2 += v * a_dst[c];
    }
#pragma unroll
    for (int o = 16; o; o >>= 1) {
        s1 += __shfl_down_sync(0xffffffff, s1, o);
        s2 += __shfl_down_sync(0xffffffff, s2, o);
    }
    if (lane == 0) { g_asrc[warp] = s1; g_adst[warp] = s2; }
}

// ------------------------- CSR build kernels --------------------------------
__global__ void zero_deg_kernel(int n)
{
    int i = blockIdx.x * blockDim.x + threadIdx.x;
    if (i < n) g_deg[i] = 0;
}

__global__ void hist_kernel(const void* __restrict__ ei, int E, int n)
{
    int t = blockIdx.x * blockDim.x + threadIdx.x;
    if (t >= E + n) return;
    int d = (t < E) ? edge_at(ei, (long long)E + t) : (t - E);
    if ((unsigned)d >= (unsigned)n) return;
    atomicAdd(&g_deg[d], 1);
}

// ---- parallel 3-phase scan ----
__global__ void scan1_kernel(int n)
{
    __shared__ int wsum[32];
    int tid = threadIdx.x;
    int i = blockIdx.x * 1024 + tid;
    int v = (i < n) ? g_deg[i] : 0;
    int s = v;
#pragma unroll
    for (int o = 16; o; o >>= 1) s += __shfl_down_sync(0xffffffff, s, o);
    if ((tid & 31) == 0) wsum[tid >> 5] = s;
    __syncthreads();
    if (tid < 32) {
        int t = wsum[tid];
#pragma unroll
        for (int o = 16; o; o >>= 1) t += __shfl_down_sync(0xffffffff, t, o);
        if (tid == 0) g_blksum[blockIdx.x] = t;
    }
}
__global__ void scan2_kernel(int nb)
{
    int tid = threadIdx.x;  // 64 threads
    int v = (tid < nb) ? g_blksum[tid] : 0;
    int x = v;
    __shared__ int sh[64];
    sh[tid] = v;
    __syncthreads();
    for (int o = 1; o < 64; o <<= 1) {
        int t = (tid >= o) ? sh[tid - o] : 0;
        __syncthreads();
        sh[tid] += t;
        __syncthreads();
    }
    if (tid < nb) g_blkoff[tid] = sh[tid] - x;  // exclusive
}
__global__ void scan3_kernel(int n)
{
    __shared__ int wsum[32];
    int tid = threadIdx.x;
    int lane = tid & 31, wid = tid >> 5;
    int i = blockIdx.x * 1024 + tid;
    int v = (i < n) ? g_deg[i] : 0;
    int x = v;
#pragma unroll
    for (int o = 1; o < 32; o <<= 1) {
        int t = __shfl_up_sync(0xffffffff, x, o);
        if (lane >= o) x += t;
    }
    if (lane == 31) wsum[wid] = x;
    __syncthreads();
    if (wid == 0) {
        int w = wsum[lane];
#pragma unroll
        for (int o = 1; o < 32; o <<= 1) {
            int t = __shfl_up_sync(0xffffffff, w, o);
            if (lane >= o) w += t;
        }
        wsum[lane] = w;
    }
    __syncthreads();
    int excl = x - v + (wid ? wsum[wid - 1] : 0) + g_blkoff[blockIdx.x];
    if (i < n) {
        g_off[i] = excl;
        g_cursor[i] = excl;
        if (i == n - 1) g_off[n] = excl + v;
    }
}

__global__ void scatter_kernel(const void* __restrict__ ei, int E, int n)
{
    int t = blockIdx.x * blockDim.x + threadIdx.x;
    if (t >= E + n) return;
    int s, d;
    if (t < E) {
        s = edge_at(ei, t);
        d = edge_at(ei, (long long)E + t);
    } else {
        s = t - E; d = t - E;
    }
    if ((unsigned)d >= (unsigned)n || (unsigned)s >= (unsigned)n) return;
    int p = atomicAdd(&g_cursor[d], 1);
    g_srcs[p] = s;
}

// =====================================================================
// GAT aggregation + fused GroupNorm(8)+ELU.  One WARP per node; lane l
// owns channels [8l, 8l+8) = exactly one GN group (all in-register).
// Softmax without max-subtraction (alpha ratio identical; |e| small).
// =====================================================================
__global__ void gat_agg_kernel(const float* __restrict__ bias,
                               const float* __restrict__ gn_w,
                               const float* __restrict__ gn_b,
                               int out_id, int n)
{
    float* out = resolve_buf(out_id, nullptr);
    int warp = (blockIdx.x * blockDim.x + threadIdx.x) >> 5;
    int lane = threadIdx.x & 31;
    if (warp >= n) return;
    int s0 = g_off[warp], s1 = g_off[warp + 1];
    float ad = g_adst[warp];

    // pass 1: s = sum over edges of exp(leaky_relu(asrc+adst))
    float s = 0.f;
    for (int j = s0 + lane; j < s1; j += 32) {
        float e = g_asrc[g_srcs[j]] + ad;
        e = (e > 0.f) ? e : 0.2f * e;
        s += expf(e);
    }
#pragma unroll
    for (int o = 16; o; o >>= 1) s += __shfl_xor_sync(0xffffffffu, s, o);
    float rinv = 1.0f / (s + 1e-16f);

    // pass 2: weighted accumulate; each lane holds 8 channels
    float acc[8] = {0.f, 0.f, 0.f, 0.f, 0.f, 0.f, 0.f, 0.f};
    for (int base = s0; base < s1; base += 32) {
        int j = base + lane;
        int sn = 0; float al = 0.f;
        if (j < s1) {
            sn = g_srcs[j];
            float e = g_asrc[sn] + ad;
            e = (e > 0.f) ? e : 0.2f * e;
            al = expf(e) * rinv;
        }
        int cnt = min(32, s1 - base);
        for (int k = 0; k < cnt; k++) {
            int   src = __shfl_sync(0xffffffffu, sn, k);
            float a   = __shfl_sync(0xffffffffu, al, k);
            const float4* hp = (const float4*)(g_bufH + (size_t)src * 256 + lane * 8);
            float4 h0 = hp[0];
            float4 h1 = hp[1];
            acc[0] += a * h0.x; acc[1] += a * h0.y;
            acc[2] += a * h0.z; acc[3] += a * h0.w;
            acc[4] += a * h1.x; acc[5] += a * h1.y;
            acc[6] += a * h1.z; acc[7] += a * h1.w;
        }
    }

    // fused GroupNorm(8)+ELU — lane's 8 channels = one full group
    int c0 = lane * 8;
    float v[8];
#pragma unroll
    for (int i = 0; i < 8; i++) v[i] = acc[i] + bias[c0 + i];
    gn8_elu(v, gn_w, gn_b, c0);
    float* orow = out + (size_t)warp * 256 + c0;
    *(float4*)(orow)     = make_float4(v[0], v[1], v[2], v[3]);
    *(float4*)(orow + 4) = make_float4(v[4], v[5], v[6], v[7]);
}

// ============================== launcher =====================================
extern "C" void kernel_launch(void* const* d_in, const int* in_sizes, int n_in,
                              void* d_out, int out_size)
{
    const float* x      = (const float*)d_in[0];
    const void*  ei     = d_in[1];
    const float* pre_w  = (const float*)d_in[2];
    const float* pre_b  = (const float*)d_in[3];
    const float* lin1_w = (const float*)d_in[4];
    const float* lin1_b = (const float*)d_in[5];
    const float* n1_w   = (const float*)d_in[6];
    const float* n1_b   = (const float*)d_in[7];
    const float* g1_w   = (const float*)d_in[8];
    const float* g1_as  = (const float*)d_in[9];
    const float* g1_ad  = (const float*)d_in[10];
    const float* g1_b   = (const float*)d_in[11];
    const float* n2_w   = (const float*)d_in[12];
    const float* n2_b   = (const float*)d_in[13];
    const float* g2_w   = (const float*)d_in[14];
    const float* g2_as  = (const float*)d_in[15];
    const float* g2_ad  = (const float*)d_in[16];
    const float* g2_b   = (const float*)d_in[17];
    const float* n3_w   = (const float*)d_in[18];
    const float* n3_b   = (const float*)d_in[19];
    const float* lin2_w = (const float*)d_in[20];
    const float* lin2_b = (const float*)d_in[21];
    const float* skip_w = (const float*)d_in[22];
    const float* skip_b = (const float*)d_in[23];
    float* out = (float*)d_out;

    int N = in_sizes[0] / CIN;
    int E = in_sizes[1] / 2;
    int ET = E + N;

    int warpBlocks = (N * 32 + 255) / 256;
    int eBlocks    = (ET + 255) / 256;
    int nBlocks    = (N + 255) / 256;
    int mBlocks    = (N + 127) / 128;
    int sBlocks    = (N + 1023) / 1024;

    // ---- CSR build start ----
    detect_dtype_kernel<<<1, 32>>>(ei, N);
    zero_deg_kernel<<<nBlocks, 256>>>(N);
    hist_kernel<<<eBlocks, 256>>>(ei, E, N);
    scan1_kernel<<<sBlocks, 1024>>>(N);
    scan2_kernel<<<1, 64>>>(sBlocks);

    // ---- lin1: x --(fused pre_norm GN+ELU on A)--> GEMM --(fused GN1+ELU)--> bufB
    bfgemm_kernel<true, true, true><<<dim3(HDIM / 64, mBlocks), 256>>>(
        BUF_EXT, x, lin1_w, lin1_b, pre_w, pre_b, n1_w, n1_b,
        BUF_B, nullptr, N, HDIM);

    scan3_kernel<<<sBlocks, 1024>>>(N);
    scatter_kernel<<<eBlocks, 256>>>(ei, E, N);

    // ---- GAT layer 1 : bufB -> (h=bufH) -> bufA (agg + fused GN2+ELU) ----
    bfgemm_kernel<false, false, false><<<dim3(HDIM / 64, mBlocks), 256>>>(
        BUF_B, nullptr, g1_w, nullptr, nullptr, nullptr, nullptr, nullptr,
        BUF_H, nullptr, N, HDIM);
    node_dots_kernel<<<warpBlocks, 256>>>(g1_as, g1_ad, N);
    gat_agg_kernel<<<warpBlocks, 256>>>(g1_b, n2_w, n2_b, BUF_A, N);

    // ---- GAT layer 2 : bufA -> (h=bufH) -> bufB (agg + fused GN3+ELU) ----
    bfgemm_kernel<false, false, false><<<dim3(HDIM / 64, mBlocks), 256>>>(
        BUF_A, nullptr, g2_w, nullptr, nullptr, nullptr, nullptr, nullptr,
        BUF_H, nullptr, N, HDIM);
    node_dots_kernel<<<warpBlocks, 256>>>(g2_as, g2_ad, N);
    gat_agg_kernel<<<warpBlocks, 256>>>(g2_b, n3_w, n3_b, BUF_B, N);

    // ---- fused lin2 + skip -> out (single pass, no ACC read) ----
    dualgemm_kernel<<<dim3(COUT / 64, mBlocks), 256>>>(
        x, lin2_w, skip_w, lin2_b, skip_b, out, N, COUT);
}